// round 1
// baseline (speedup 1.0000x reference)
#include <cuda_runtime.h>
#include <math.h>
#include <stdint.h>

#define B_  32
#define S_  2048
#define H_  1024
#define BS_ (B_ * S_)

typedef unsigned long long u64;

// ---------------- scratch (device globals: no allocations allowed) ----------
__device__ float g_scores[BS_];     // [B,S] pre-softmax logits
__device__ float g_bias2[B_ * H_];  // [B,H] hidden@W^T + b_attn

// ---------------- packed f32x2 helpers (Blackwell FFMA2) --------------------
__device__ __forceinline__ void ffma2(u64 &c, u64 a, u64 b) {
    asm("fma.rn.f32x2 %0, %1, %2, %0;" : "+l"(c) : "l"(a), "l"(b));
}
__device__ __forceinline__ u64 dup2(float x) {
    u64 r;
    asm("mov.b64 %0, {%1, %1};" : "=l"(r) : "r"(__float_as_uint(x)));
    return r;
}
__device__ __forceinline__ void unpk(u64 x, float &lo, float &hi) {
    unsigned int a, b;
    asm("mov.b64 {%0, %1}, %2;" : "=r"(a), "=r"(b) : "l"(x));
    lo = __uint_as_float(a);
    hi = __uint_as_float(b);
}

union F4 { float4 f; u64 u[2]; };

// ---------------- kernel 0: zero scores + context region --------------------
__global__ void zero_kernel(float* __restrict__ ctx) {
    int i = blockIdx.x * blockDim.x + threadIdx.x;   // 65536 threads
    if (i < BS_)      g_scores[i] = 0.0f;
    if (i < B_ * H_)  ctx[i]      = 0.0f;
}

// ---------------- kernel 1: bias2 = hidden @ W^T + b_attn -------------------
// grid (B, H/8), 256 threads (8 warps); warp w computes one output o.
__global__ void bias2_kernel(const float* __restrict__ hidden,
                             const float* __restrict__ W,
                             const float* __restrict__ b_attn) {
    __shared__ float sh[H_];
    const int b = blockIdx.x;
    for (int i = threadIdx.x; i < H_; i += blockDim.x) sh[i] = hidden[b * H_ + i];
    __syncthreads();

    const int w    = threadIdx.x >> 5;
    const int lane = threadIdx.x & 31;
    const int o    = blockIdx.y * 8 + w;
    const float* wr = W + (size_t)o * H_;

    float sum = 0.0f;
#pragma unroll
    for (int h = lane * 4; h < H_; h += 128) {
        float4 wv = *(const float4*)(wr + h);
        float4 xv = *(const float4*)(sh + h);
        sum += wv.x * xv.x + wv.y * xv.y + wv.z * xv.z + wv.w * xv.w;
    }
#pragma unroll
    for (int off = 16; off; off >>= 1)
        sum += __shfl_xor_sync(0xffffffffu, sum, off);
    if (lane == 0) g_bias2[b * H_ + o] = sum + b_attn[o];
}

// ---------------- kernel 2: fused energy GEMM + tanh + dot(v) ---------------
// scores[b,s] = sum_o v[o] * tanh( enc[b,s]·W[o] + bias2[b,o] )
// Block tile: 128 rows x 128 o, TK=8, double-buffered SMEM (stride 132 pad),
// 8x8 per-thread micro-tile with f32x2-packed accumulators (cols paired).
// grid: (H/128 = 8 [fast, keeps enc single-pass], BS/128 = 512)
__global__ __launch_bounds__(256, 2)
void energy_kernel(const float* __restrict__ enc,
                   const float* __restrict__ W,
                   const float* __restrict__ v) {
    __shared__ float As[2][8][132];
    __shared__ float Bs[2][8][132];

    const int tid = threadIdx.x;
    const int tx  = tid & 15;          // col group 0..15
    const int ty  = tid >> 4;          // row group 0..15
    const int oBase   = blockIdx.x * 128;
    const int rowBase = blockIdx.y * 128;
    const int b       = rowBase >> 11;     // 2048 rows per batch, 128 | 2048

    // loader mapping: 2 threads per row, one float4 (4 k) each
    const int lrow = tid >> 1;             // 0..127
    const int lk   = (tid & 1) * 4;        // 0 or 4

    const float* aPtr = enc + (size_t)(rowBase + lrow) * H_ + lk;
    const float* bPtr = W   + (size_t)(oBase  + lrow) * H_ + lk;

    u64 acc[8][4];
#pragma unroll
    for (int i = 0; i < 8; ++i)
#pragma unroll
        for (int j = 0; j < 4; ++j) acc[i][j] = 0ull;

    // prologue: chunk 0 -> buffer 0
    {
        float4 aR = *(const float4*)(aPtr);
        float4 bR = *(const float4*)(bPtr);
        As[0][lk + 0][lrow] = aR.x;  As[0][lk + 1][lrow] = aR.y;
        As[0][lk + 2][lrow] = aR.z;  As[0][lk + 3][lrow] = aR.w;
        Bs[0][lk + 0][lrow] = bR.x;  Bs[0][lk + 1][lrow] = bR.y;
        Bs[0][lk + 2][lrow] = bR.z;  Bs[0][lk + 3][lrow] = bR.w;
    }
    __syncthreads();

    int buf = 0;
    for (int kt = 0; kt < 128; ++kt) {
        float4 aN, bN;
        if (kt < 127) {
            aN = *(const float4*)(aPtr + (kt + 1) * 8);
            bN = *(const float4*)(bPtr + (kt + 1) * 8);
        }

#pragma unroll
        for (int k = 0; k < 8; ++k) {
            float4 av0 = *(const float4*)&As[buf][k][ty * 4];
            float4 av1 = *(const float4*)&As[buf][k][64 + ty * 4];
            F4 bv0, bv1;
            bv0.f = *(const float4*)&Bs[buf][k][tx * 4];
            bv1.f = *(const float4*)&Bs[buf][k][64 + tx * 4];

            u64 ad[8];
            ad[0] = dup2(av0.x); ad[1] = dup2(av0.y);
            ad[2] = dup2(av0.z); ad[3] = dup2(av0.w);
            ad[4] = dup2(av1.x); ad[5] = dup2(av1.y);
            ad[6] = dup2(av1.z); ad[7] = dup2(av1.w);

#pragma unroll
            for (int i = 0; i < 8; ++i) {
                ffma2(acc[i][0], ad[i], bv0.u[0]);
                ffma2(acc[i][1], ad[i], bv0.u[1]);
                ffma2(acc[i][2], ad[i], bv1.u[0]);
                ffma2(acc[i][3], ad[i], bv1.u[1]);
            }
        }

        if (kt < 127) {
            const int nb = buf ^ 1;
            As[nb][lk + 0][lrow] = aN.x;  As[nb][lk + 1][lrow] = aN.y;
            As[nb][lk + 2][lrow] = aN.z;  As[nb][lk + 3][lrow] = aN.w;
            Bs[nb][lk + 0][lrow] = bN.x;  Bs[nb][lk + 1][lrow] = bN.y;
            Bs[nb][lk + 2][lrow] = bN.z;  Bs[nb][lk + 3][lrow] = bN.w;
            __syncthreads();
            buf = nb;
        }
    }

    // epilogue: tanh(acc + bias2) * v, reduce over this block's 128 o's
    float vv[8], bb[8];
#pragma unroll
    for (int j = 0; j < 8; ++j) {
        const int n = oBase + ((j < 4) ? (tx * 4 + j) : (64 + tx * 4 + j - 4));
        vv[j] = v[n];
        bb[j] = g_bias2[b * H_ + n];
    }

#pragma unroll
    for (int i = 0; i < 8; ++i) {
        float p = 0.0f;
#pragma unroll
        for (int jp = 0; jp < 4; ++jp) {
            float lo, hi;
            unpk(acc[i][jp], lo, hi);
            const int j0 = 2 * jp, j1 = 2 * jp + 1;
            p += tanhf(lo + bb[j0]) * vv[j0];
            p += tanhf(hi + bb[j1]) * vv[j1];
        }
        // reduce across the 16 col-group lanes (same rows)
#pragma unroll
        for (int off = 8; off; off >>= 1)
            p += __shfl_xor_sync(0xffffffffu, p, off, 16);
        if (tx == 0) {
            const int m = rowBase + ((i < 4) ? (ty * 4 + i) : (64 + ty * 4 + i - 4));
            atomicAdd(&g_scores[m], p);
        }
    }
}

// ---------------- kernel 3: softmax over S per batch ------------------------
__global__ void softmax_kernel(float* __restrict__ attn) {
    __shared__ float red[8];
    const int b = blockIdx.x, t = threadIdx.x;
    const float* s = g_scores + b * S_;

    float loc[8];
    float mx = -1e30f;
#pragma unroll
    for (int i = 0; i < 8; ++i) {
        loc[i] = s[t + i * 256];
        mx = fmaxf(mx, loc[i]);
    }
#pragma unroll
    for (int off = 16; off; off >>= 1)
        mx = fmaxf(mx, __shfl_xor_sync(0xffffffffu, mx, off));
    if ((t & 31) == 0) red[t >> 5] = mx;
    __syncthreads();
    float bm = red[0];
#pragma unroll
    for (int w = 1; w < 8; ++w) bm = fmaxf(bm, red[w]);
    __syncthreads();

    float sum = 0.0f;
#pragma unroll
    for (int i = 0; i < 8; ++i) {
        loc[i] = expf(loc[i] - bm);
        sum += loc[i];
    }
#pragma unroll
    for (int off = 16; off; off >>= 1)
        sum += __shfl_xor_sync(0xffffffffu, sum, off);
    if ((t & 31) == 0) red[t >> 5] = sum;
    __syncthreads();
    float bs = 0.0f;
#pragma unroll
    for (int w = 0; w < 8; ++w) bs += red[w];

    const float inv = 1.0f / bs;
#pragma unroll
    for (int i = 0; i < 8; ++i)
        attn[b * S_ + t + i * 256] = loc[i] * inv;
}

// ---------------- kernel 4: context = attn @ enc ----------------------------
// grid (B, 16): each block handles 128 s positions, all 1024 h (4 per thread)
__global__ void context_kernel(const float* __restrict__ enc,
                               const float* __restrict__ attn,
                               float* __restrict__ ctx) {
    __shared__ float ws[128];
    const int b  = blockIdx.x;
    const int s0 = blockIdx.y * 128;
    if (threadIdx.x < 128) ws[threadIdx.x] = attn[b * S_ + s0 + threadIdx.x];
    __syncthreads();

    const int h = threadIdx.x * 4;
    float4 acc = make_float4(0.f, 0.f, 0.f, 0.f);
    const float* base = enc + ((size_t)b * S_ + s0) * H_ + h;
#pragma unroll 4
    for (int s = 0; s < 128; ++s) {
        const float w = ws[s];
        float4 e = *(const float4*)(base + (size_t)s * H_);
        acc.x += w * e.x;  acc.y += w * e.y;
        acc.z += w * e.z;  acc.w += w * e.w;
    }
    atomicAdd(&ctx[b * H_ + h + 0], acc.x);
    atomicAdd(&ctx[b * H_ + h + 1], acc.y);
    atomicAdd(&ctx[b * H_ + h + 2], acc.z);
    atomicAdd(&ctx[b * H_ + h + 3], acc.w);
}

// ---------------- launch ----------------------------------------------------
extern "C" void kernel_launch(void* const* d_in, const int* in_sizes, int n_in,
                              void* d_out, int out_size) {
    const float* hidden = (const float*)d_in[0];   // [B,H]
    const float* enc    = (const float*)d_in[1];   // [B,S,H]
    const float* W      = (const float*)d_in[2];   // [H,H]
    const float* b_attn = (const float*)d_in[3];   // [H]
    const float* v      = (const float*)d_in[4];   // [H]

    float* out  = (float*)d_out;
    float* ctx  = out;             // [B,H]  = 32768 floats
    float* attn = out + B_ * H_;   // [B,S]  = 65536 floats

    zero_kernel<<<256, 256>>>(ctx);
    bias2_kernel<<<dim3(B_, H_ / 8), 256>>>(hidden, W, b_attn);
    energy_kernel<<<dim3(H_ / 128, BS_ / 128), 256>>>(enc, W, v);
    softmax_kernel<<<B_, 256>>>(attn);
    context_kernel<<<dim3(B_, 16), 256>>>(enc, attn, ctx);
}

// round 6
// speedup vs baseline: 1.6339x; 1.6339x over previous
#include <cuda_runtime.h>
#include <cuda.h>
#include <cuda_bf16.h>
#include <math.h>
#include <stdint.h>

#define B_  32
#define S_  2048
#define H_  1024
#define BS_ (B_ * S_)

// ---------------- scratch (small! large planes are forbidden) ---------------
__device__ __align__(1024) float g_scores[BS_];     // [B,S] logits
__device__ __align__(1024) float g_bias2[B_ * H_];  // [B,H]

// =================== PTX helpers (baseline sm_100: TMA + mbarrier + mma) ====
__device__ __forceinline__ uint32_t smem_u32(const void* p) {
    uint32_t a;
    asm("{ .reg .u64 t; cvta.to.shared.u64 t, %1; cvt.u32.u64 %0, t; }"
        : "=r"(a) : "l"(p));
    return a;
}
__device__ __forceinline__ void mbar_init(uint32_t m, uint32_t cnt) {
    asm volatile("mbarrier.init.shared.b64 [%0], %1;" :: "r"(m), "r"(cnt) : "memory");
}
__device__ __forceinline__ void mbar_expect_tx(uint32_t m, uint32_t bytes) {
    asm volatile("mbarrier.arrive.expect_tx.shared.b64 _, [%0], %1;"
                 :: "r"(m), "r"(bytes) : "memory");
}
__device__ __forceinline__ void mbar_wait(uint32_t m, uint32_t phase) {
    asm volatile(
        "{\n\t.reg .pred P;\n"
        "W_%=:\n\t"
        "mbarrier.try_wait.parity.shared::cta.b64 P, [%0], %1, 0x989680;\n\t"
        "@P bra D_%=;\n\t"
        "bra W_%=;\n"
        "D_%=:\n\t}"
        :: "r"(m), "r"(phase) : "memory");
}
__device__ __forceinline__ void mbar_inval(uint32_t m) {
    asm volatile("mbarrier.inval.shared.b64 [%0];" :: "r"(m) : "memory");
}
__device__ __forceinline__ void tma_load_2d(uint32_t dst, const void* map,
                                            int cx, int cy, uint32_t mbar) {
    asm volatile(
        "cp.async.bulk.tensor.2d.shared::cta.global.tile.mbarrier::complete_tx::bytes "
        "[%0], [%1, {%2, %3}], [%4];"
        :: "r"(dst), "l"(map), "r"(cx), "r"(cy), "r"(mbar) : "memory");
}
__device__ __forceinline__ void ldsm4(uint32_t r[4], uint32_t addr) {
    asm volatile("ldmatrix.sync.aligned.m8n8.x4.shared.b16 {%0,%1,%2,%3}, [%4];"
                 : "=r"(r[0]), "=r"(r[1]), "=r"(r[2]), "=r"(r[3]) : "r"(addr));
}
__device__ __forceinline__ void mma16816(float c[4], const uint32_t a[4],
                                         uint32_t b0, uint32_t b1) {
    asm volatile(
        "mma.sync.aligned.m16n8k16.row.col.f32.bf16.bf16.f32 "
        "{%0,%1,%2,%3}, {%4,%5,%6,%7}, {%8,%9}, {%0,%1,%2,%3};"
        : "+f"(c[0]), "+f"(c[1]), "+f"(c[2]), "+f"(c[3])
        : "r"(a[0]), "r"(a[1]), "r"(a[2]), "r"(a[3]), "r"(b0), "r"(b1));
}
__device__ __forceinline__ uint32_t pack_bf16(float lo_e, float hi_e) {
    // word = {low half = bf16(lo_e), high half = bf16(hi_e)}
    uint32_t r;
    asm("cvt.rn.bf16x2.f32 %0, %1, %2;" : "=r"(r) : "f"(hi_e), "f"(lo_e));
    return r;
}

// ---------------- SMEM layout for energy_mma ---------------------------------
// mbar 0..24 | bias 64..576 | v 576..1088 | fp32 stages @2048 | bf16 @100352
// (R5 bug: fp32 stages at 1024 overlapped v[112..127]. Fixed: base 2048.)
#define SM_FULL(i)     ((i) * 8)
#define SM_BIAS        64
#define SM_V           576
#define SM_F32         2048
#define F32_STAGE      32768
#define SM_BF16        (SM_F32 + 3 * F32_STAGE)          // 100352
#define BF_BUF         32768
#define BF_ALO         8192
#define BF_BHI         16384
#define BF_BLO         24576
#define SM_TOTAL       (SM_BF16 + 2 * BF_BUF)            // 165888

// ---------------- kernel 0: zero scores + context region --------------------
__global__ void zero_kernel(float* __restrict__ ctx) {
    int i = blockIdx.x * blockDim.x + threadIdx.x;   // 65536 threads
    if (i < BS_)      g_scores[i] = 0.0f;
    if (i < B_ * H_)  ctx[i]      = 0.0f;
}

// ---------------- kernel 1: bias2 = hidden @ W^T + b_attn -------------------
__global__ void bias2_kernel(const float* __restrict__ hidden,
                             const float* __restrict__ W,
                             const float* __restrict__ b_attn) {
    __shared__ float sh[H_];
    const int b = blockIdx.x;
    for (int i = threadIdx.x; i < H_; i += blockDim.x) sh[i] = hidden[b * H_ + i];
    __syncthreads();

    const int w    = threadIdx.x >> 5;
    const int lane = threadIdx.x & 31;
    const int o    = blockIdx.y * 8 + w;
    const float* wr = W + (size_t)o * H_;

    float sum = 0.0f;
#pragma unroll
    for (int h = lane * 4; h < H_; h += 128) {
        float4 wv = *(const float4*)(wr + h);
        float4 xv = *(const float4*)(sh + h);
        sum += wv.x * xv.x + wv.y * xv.y + wv.z * xv.z + wv.w * xv.w;
    }
#pragma unroll
    for (int off = 16; off; off >>= 1)
        sum += __shfl_xor_sync(0xffffffffu, sum, off);
    if (lane == 0) g_bias2[b * H_ + o] = sum + b_attn[o];
}

// ---------------- kernel 2: TMA fp32 -> bf16 split -> mma.sync --------------
// scores[b,s] += sum_o v[o]*tanh(enc[s]·W[o] + bias2[b,o])
// bf16x3: x*w ~ xh*wh + xh*wl + xl*wh (fp32 accum). CTA 128x128, K-chunk 32.
__device__ __forceinline__ float fast_tanh(float x) {
    float t = __expf(-2.0f * fabsf(x));
    float r = __fdividef(1.0f - t, 1.0f + t);
    return copysignf(r, x);
}

__global__ void __launch_bounds__(256, 1)
energy_mma(const __grid_constant__ CUtensorMap mapA,
           const __grid_constant__ CUtensorMap mapB,
           const float* __restrict__ v) {
    extern __shared__ __align__(1024) char smem[];
    const uint32_t sb  = smem_u32(smem);
    const int tid  = threadIdx.x;
    const int wid  = tid >> 5;
    const int lane = tid & 31;
    const int oBase   = blockIdx.x * 128;
    const int rowBase = blockIdx.y * 128;
    const int b       = rowBase >> 11;

    const int warpM = (wid >> 2) * 64;   // 0 or 64
    const int warpN = (wid & 3) * 32;    // 0,32,64,96

    if (tid == 0) {
#pragma unroll
        for (int i = 0; i < 3; ++i) mbar_init(sb + SM_FULL(i), 1);
    }
    if (tid < 128) {
        ((float*)(smem + SM_BIAS))[tid] = g_bias2[b * H_ + oBase + tid];
        ((float*)(smem + SM_V))[tid]    = v[oBase + tid];
    }
    __syncthreads();

    if (tid == 0) {
#pragma unroll
        for (int c = 0; c < 3; ++c) {
            const uint32_t st = sb + SM_F32 + c * F32_STAGE;
            mbar_expect_tx(sb + SM_FULL(c), F32_STAGE);
            tma_load_2d(st,         &mapA, c * 32, rowBase, sb + SM_FULL(c));
            tma_load_2d(st + 16384, &mapB, c * 32, oBase,   sb + SM_FULL(c));
        }
    }

    // ---- conversion mapping: threads 0..127 -> A row tid, 128..255 -> B row
    const int cr   = tid & 127;              // row in tile
    const int cmat = tid >> 7;               // 0 = A, 1 = B
    const int xr   = cr & 7;                 // fp32 swizzle (TMA SW128, 128B rows)
    const int xr2  = (cr >> 1) & 3;          // bf16 swizzle (64B rows)
    const uint32_t cSrcRow = (uint32_t)(cmat * 16384 + cr * 128);
    const uint32_t cDstRow = (uint32_t)(cmat * 16384 + cr * 64);

    // ---- mma fragment mapping
    const int rA = (lane & 7) + (((lane >> 3) & 1) << 3);
    const int gA = (lane >> 4) & 1;
    const int rB = (lane & 7) + (((lane >> 4) & 1) << 3);
    const int gB = (lane >> 3) & 1;
    const int xA2 = (rA >> 1) & 3;
    const int xB2 = (rB >> 1) & 3;

    float acc[4][4][4];
#pragma unroll
    for (int i = 0; i < 4; ++i)
#pragma unroll
        for (int j = 0; j < 4; ++j)
#pragma unroll
            for (int k = 0; k < 4; ++k) acc[i][j][k] = 0.0f;

    // ---- prologue: convert chunk 0 into bf16 buf 0
    {
        mbar_wait(sb + SM_FULL(0), 0);
        const char* src = smem + SM_F32 + cSrcRow;
        char* dhi = (char*)smem + SM_BF16 + cDstRow;
        char* dlo = dhi + BF_ALO;
#pragma unroll
        for (int cb = 0; cb < 4; ++cb) {
            float4 xa = *(const float4*)(src + (((2 * cb)     ^ xr) << 4));
            float4 xb = *(const float4*)(src + (((2 * cb + 1) ^ xr) << 4));
            uint4 hw, lw;
            hw.x = pack_bf16(xa.x, xa.y);  hw.y = pack_bf16(xa.z, xa.w);
            hw.z = pack_bf16(xb.x, xb.y);  hw.w = pack_bf16(xb.z, xb.w);
            float r0 = xa.x - __bfloat162float(__float2bfloat16_rn(xa.x));
            float r1 = xa.y - __bfloat162float(__float2bfloat16_rn(xa.y));
            float r2 = xa.z - __bfloat162float(__float2bfloat16_rn(xa.z));
            float r3 = xa.w - __bfloat162float(__float2bfloat16_rn(xa.w));
            float r4 = xb.x - __bfloat162float(__float2bfloat16_rn(xb.x));
            float r5 = xb.y - __bfloat162float(__float2bfloat16_rn(xb.y));
            float r6 = xb.z - __bfloat162float(__float2bfloat16_rn(xb.z));
            float r7 = xb.w - __bfloat162float(__float2bfloat16_rn(xb.w));
            lw.x = pack_bf16(r0, r1);  lw.y = pack_bf16(r2, r3);
            lw.z = pack_bf16(r4, r5);  lw.w = pack_bf16(r6, r7);
            const int so = (cb ^ xr2) << 4;
            *(uint4*)(dhi + so) = hw;
            *(uint4*)(dlo + so) = lw;
        }
    }
    __syncthreads();

#pragma unroll 1
    for (int kt = 0; kt < 32; ++kt) {
        // refill: chunk kt+3 into slot kt%3 (chunk kt consumed last iteration)
        if (tid == 0 && kt + 3 < 32) {
            const int c = kt + 3;
            const uint32_t st = sb + SM_F32 + (c % 3) * F32_STAGE;
            mbar_expect_tx(sb + SM_FULL(c % 3), F32_STAGE);
            tma_load_2d(st,         &mapA, c * 32, rowBase, sb + SM_FULL(c % 3));
            tma_load_2d(st + 16384, &mapB, c * 32, oBase,   sb + SM_FULL(c % 3));
        }

        // conversion of chunk kt+1 (into buf (kt+1)&1) — overlaps mma below
        if (kt + 1 < 32) {
            const int c = kt + 1;
            mbar_wait(sb + SM_FULL(c % 3), (c / 3) & 1);
            const char* src = smem + SM_F32 + (c % 3) * F32_STAGE + cSrcRow;
            char* dhi = (char*)smem + SM_BF16 + ((c & 1) * BF_BUF) + cDstRow;
            char* dlo = dhi + BF_ALO;
#pragma unroll
            for (int cb = 0; cb < 4; ++cb) {
                float4 xa = *(const float4*)(src + (((2 * cb)     ^ xr) << 4));
                float4 xb = *(const float4*)(src + (((2 * cb + 1) ^ xr) << 4));
                uint4 hw, lw;
                hw.x = pack_bf16(xa.x, xa.y);  hw.y = pack_bf16(xa.z, xa.w);
                hw.z = pack_bf16(xb.x, xb.y);  hw.w = pack_bf16(xb.z, xb.w);
                float r0 = xa.x - __bfloat162float(__float2bfloat16_rn(xa.x));
                float r1 = xa.y - __bfloat162float(__float2bfloat16_rn(xa.y));
                float r2 = xa.z - __bfloat162float(__float2bfloat16_rn(xa.z));
                float r3 = xa.w - __bfloat162float(__float2bfloat16_rn(xa.w));
                float r4 = xb.x - __bfloat162float(__float2bfloat16_rn(xb.x));
                float r5 = xb.y - __bfloat162float(__float2bfloat16_rn(xb.y));
                float r6 = xb.z - __bfloat162float(__float2bfloat16_rn(xb.z));
                float r7 = xb.w - __bfloat162float(__float2bfloat16_rn(xb.w));
                lw.x = pack_bf16(r0, r1);  lw.y = pack_bf16(r2, r3);
                lw.z = pack_bf16(r4, r5);  lw.w = pack_bf16(r6, r7);
                const int so = (cb ^ xr2) << 4;
                *(uint4*)(dhi + so) = hw;
                *(uint4*)(dlo + so) = lw;
            }
        }

        // mma on bf16 buf kt&1 (written last iteration, synced)
        {
            const uint32_t bufb = sb + SM_BF16 + (kt & 1) * BF_BUF;
            const uint32_t AH = bufb;
            const uint32_t AL = bufb + BF_ALO;
            const uint32_t BH = bufb + BF_BHI;
            const uint32_t BL = bufb + BF_BLO;
#pragma unroll
            for (int k16 = 0; k16 < 2; ++k16) {
                const int cA = ((2 * k16 + gA) ^ xA2) << 4;
                const int cB = ((2 * k16 + gB) ^ xB2) << 4;
                uint32_t ah[4][4], al[4][4], bh[2][4], bl[2][4];
#pragma unroll
                for (int mi = 0; mi < 4; ++mi)
                    ldsm4(ah[mi], AH + (warpM + mi * 16 + rA) * 64 + cA);
#pragma unroll
                for (int np = 0; np < 2; ++np)
                    ldsm4(bh[np], BH + (warpN + np * 16 + rB) * 64 + cB);
#pragma unroll
                for (int np = 0; np < 2; ++np)
                    ldsm4(bl[np], BL + (warpN + np * 16 + rB) * 64 + cB);
#pragma unroll
                for (int mi = 0; mi < 4; ++mi)
                    ldsm4(al[mi], AL + (warpM + mi * 16 + rA) * 64 + cA);
                // p0: Ahi x Bhi, p1: Ahi x Blo, p2: Alo x Bhi
#pragma unroll
                for (int mi = 0; mi < 4; ++mi)
#pragma unroll
                    for (int ni = 0; ni < 4; ++ni) {
                        mma16816(acc[mi][ni], ah[mi],
                                 bh[ni >> 1][(ni & 1) * 2], bh[ni >> 1][(ni & 1) * 2 + 1]);
                        mma16816(acc[mi][ni], ah[mi],
                                 bl[ni >> 1][(ni & 1) * 2], bl[ni >> 1][(ni & 1) * 2 + 1]);
                        mma16816(acc[mi][ni], al[mi],
                                 bh[ni >> 1][(ni & 1) * 2], bh[ni >> 1][(ni & 1) * 2 + 1]);
                    }
            }
        }
        __syncthreads();
    }

    // ---- epilogue: tanh(acc + bias2)*v, reduce over n, atomicAdd scores ----
    const float* sbias = (const float*)(smem + SM_BIAS);
    const float* sv    = (const float*)(smem + SM_V);
    const int q = lane & 3;
    const int r = lane >> 2;

#pragma unroll
    for (int mi = 0; mi < 4; ++mi) {
        float pa = 0.0f, pb = 0.0f;
#pragma unroll
        for (int ni = 0; ni < 4; ++ni) {
            const int n0 = warpN + ni * 8 + 2 * q;
            const float b0 = sbias[n0], b1 = sbias[n0 + 1];
            const float v0 = sv[n0],    v1 = sv[n0 + 1];
            pa += fast_tanh(acc[mi][ni][0] + b0) * v0 +
                  fast_tanh(acc[mi][ni][1] + b1) * v1;
            pb += fast_tanh(acc[mi][ni][2] + b0) * v0 +
                  fast_tanh(acc[mi][ni][3] + b1) * v1;
        }
        pa += __shfl_xor_sync(0xffffffffu, pa, 1);
        pa += __shfl_xor_sync(0xffffffffu, pa, 2);
        pb += __shfl_xor_sync(0xffffffffu, pb, 1);
        pb += __shfl_xor_sync(0xffffffffu, pb, 2);
        if (q == 0) {
            const int m = rowBase + warpM + mi * 16 + r;
            atomicAdd(&g_scores[m], pa);
            atomicAdd(&g_scores[m + 8], pb);
        }
    }

    __syncthreads();
    if (tid == 0) {
#pragma unroll
        for (int i = 0; i < 3; ++i) mbar_inval(sb + SM_FULL(i));
    }
}

// ---------------- kernel 3: softmax over S per batch ------------------------
__global__ void softmax_kernel(float* __restrict__ attn) {
    __shared__ float red[8];
    const int b = blockIdx.x, t = threadIdx.x;
    const float* s = g_scores + b * S_;

    float loc[8];
    float mx = -1e30f;
#pragma unroll
    for (int i = 0; i < 8; ++i) {
        loc[i] = s[t + i * 256];
        mx = fmaxf(mx, loc[i]);
    }
#pragma unroll
    for (int off = 16; off; off >>= 1)
        mx = fmaxf(mx, __shfl_xor_sync(0xffffffffu, mx, off));
    if ((t & 31) == 0) red[t >> 5] = mx;
    __syncthreads();
    float bm = red[0];
#pragma unroll
    for (int w = 1; w < 8; ++w) bm = fmaxf(bm, red[w]);
    __syncthreads();

    float sum = 0.0f;
#pragma unroll
    for (int i = 0; i < 8; ++i) {
        loc[i] = expf(loc[i] - bm);
        sum += loc[i];
    }
#pragma unroll
    for (int off = 16; off; off >>= 1)
        sum += __shfl_xor_sync(0xffffffffu, sum, off);
    if ((t & 31) == 0) red[t >> 5] = sum;
    __syncthreads();
    float bs = 0.0f;
#pragma unroll
    for (int w = 0; w < 8; ++w) bs += red[w];

    const float inv = 1.0f / bs;
#pragma unroll
    for (int i = 0; i < 8; ++i)
        attn[b * S_ + t + i * 256] = loc[i] * inv;
}

// ---------------- kernel 4: context = attn @ enc ----------------------------
__global__ void context_kernel(const float* __restrict__ enc,
                               const float* __restrict__ attn,
                               float* __restrict__ ctx) {
    __shared__ float ws[128];
    const int b  = blockIdx.x;
    const int s0 = blockIdx.y * 128;
    if (threadIdx.x < 128) ws[threadIdx.x] = attn[b * S_ + s0 + threadIdx.x];
    __syncthreads();

    const int h = threadIdx.x * 4;
    float4 acc = make_float4(0.f, 0.f, 0.f, 0.f);
    const float* base = enc + ((size_t)b * S_ + s0) * H_ + h;
#pragma unroll 4
    for (int s = 0; s < 128; ++s) {
        const float w = ws[s];
        float4 e = *(const float4*)(base + (size_t)s * H_);
        acc.x += w * e.x;  acc.y += w * e.y;
        acc.z += w * e.z;  acc.w += w * e.w;
    }
    atomicAdd(&ctx[b * H_ + h + 0], acc.x);
    atomicAdd(&ctx[b * H_ + h + 1], acc.y);
    atomicAdd(&ctx[b * H_ + h + 2], acc.z);
    atomicAdd(&ctx[b * H_ + h + 3], acc.w);
}

// ---------------- host: tensormap encoding + launch -------------------------
typedef CUresult (*EncodeFn)(CUtensorMap*, CUtensorMapDataType, cuuint32_t, void*,
                             const cuuint64_t*, const cuuint64_t*, const cuuint32_t*,
                             const cuuint32_t*, CUtensorMapInterleave, CUtensorMapSwizzle,
                             CUtensorMapL2promotion, CUtensorMapFloatOOBfill);

static void encode_map_f32(EncodeFn fn, CUtensorMap* m, const void* ptr,
                           uint64_t d0, uint64_t d1) {
    uint64_t dims[2]    = {d0, d1};
    uint64_t strides[1] = {d0 * 4};        // fp32
    uint32_t box[2]     = {32, 128};       // 32 floats = 128B (SW128 limit)
    uint32_t estr[2]    = {1, 1};
    fn(m, CU_TENSOR_MAP_DATA_TYPE_FLOAT32, 2, (void*)ptr, dims, strides, box, estr,
       CU_TENSOR_MAP_INTERLEAVE_NONE, CU_TENSOR_MAP_SWIZZLE_128B,
       CU_TENSOR_MAP_L2_PROMOTION_L2_128B, CU_TENSOR_MAP_FLOAT_OOB_FILL_NONE);
}

extern "C" void kernel_launch(void* const* d_in, const int* in_sizes, int n_in,
                              void* d_out, int out_size) {
    const float* hidden = (const float*)d_in[0];   // [B,H]
    const float* enc    = (const float*)d_in[1];   // [B,S,H]
    const float* W      = (const float*)d_in[2];   // [H,H]
    const float* b_attn = (const float*)d_in[3];   // [H]
    const float* v      = (const float*)d_in[4];   // [H]

    float* out  = (float*)d_out;
    float* ctx  = out;             // [B,H]
    float* attn = out + B_ * H_;   // [B,S]

    // Executed unconditionally on EVERY call (no static guards). All
    // idempotent, non-stream APIs: capture-safe.
    cudaDriverEntryPointQueryResult st;
    void* fp = nullptr;
    cudaGetDriverEntryPoint("cuTensorMapEncodeTiled", &fp, cudaEnableDefault, &st);
    EncodeFn enc_fn = (EncodeFn)fp;
    cudaFuncSetAttribute((const void*)energy_mma,
                         cudaFuncAttributeMaxDynamicSharedMemorySize, SM_TOTAL);

    CUtensorMap mA, mB;
    encode_map_f32(enc_fn, &mA, enc, H_, BS_);
    encode_map_f32(enc_fn, &mB, W,   H_, H_);

    zero_kernel<<<256, 256>>>(ctx);
    bias2_kernel<<<dim3(B_, H_ / 8), 256>>>(hidden, W, b_attn);
    energy_mma<<<dim3(H_ / 128, BS_ / 128), 256, SM_TOTAL>>>(mA, mB, v);
    softmax_kernel<<<B_, 256>>>(attn);
    context_kernel<<<dim3(B_, 16), 256>>>(enc, attn, ctx);
}

// round 7
// speedup vs baseline: 2.2653x; 1.3864x over previous
#include <cuda_runtime.h>
#include <cuda_bf16.h>
#include <math.h>
#include <stdint.h>

#define B_  32
#define S_  2048
#define H_  1024
#define BS_ (B_ * S_)

// ---------------- scratch (small device globals only) -----------------------
__device__ __align__(1024) float g_scores[BS_];     // [B,S] logits
__device__ __align__(1024) float g_bias2[B_ * H_];  // [B,H]

// =================== PTX helpers ============================================
__device__ __forceinline__ uint32_t smem_u32(const void* p) {
    uint32_t a;
    asm("{ .reg .u64 t; cvta.to.shared.u64 t, %1; cvt.u32.u64 %0, t; }"
        : "=r"(a) : "l"(p));
    return a;
}
__device__ __forceinline__ void ldsm4(uint32_t r[4], uint32_t addr) {
    asm volatile("ldmatrix.sync.aligned.m8n8.x4.shared.b16 {%0,%1,%2,%3}, [%4];"
                 : "=r"(r[0]), "=r"(r[1]), "=r"(r[2]), "=r"(r[3]) : "r"(addr));
}
__device__ __forceinline__ void mma16816(float c[4], const uint32_t a[4],
                                         uint32_t b0, uint32_t b1) {
    asm volatile(
        "mma.sync.aligned.m16n8k16.row.col.f32.bf16.bf16.f32 "
        "{%0,%1,%2,%3}, {%4,%5,%6,%7}, {%8,%9}, {%0,%1,%2,%3};"
        : "+f"(c[0]), "+f"(c[1]), "+f"(c[2]), "+f"(c[3])
        : "r"(a[0]), "r"(a[1]), "r"(a[2]), "r"(a[3]), "r"(b0), "r"(b1));
}
__device__ __forceinline__ uint32_t pack_bf16(float lo_e, float hi_e) {
    uint32_t r;   // word = {lo half = bf16(lo_e), hi half = bf16(hi_e)}
    asm("cvt.rn.bf16x2.f32 %0, %1, %2;" : "=r"(r) : "f"(hi_e), "f"(lo_e));
    return r;
}
__device__ __forceinline__ float tob(float f) {
    return __bfloat162float(__float2bfloat16_rn(f));
}

// ---------------- SMEM layout for energy_mma --------------------------------
// bias[128] @0 | v[128] @512 | bf16 double buffer @1024 (2 x 32KB)
// buf layout: AH 0 | AL 8192 | BH 16384 | BL 24576  (128 rows x 64B, swizzled)
#define SM_BIAS   0
#define SM_V      512
#define SM_BF     1024
#define BF_BUF    32768
#define BF_ALO    8192
#define BF_BHI    16384
#define BF_BLO    24576
#define SM_TOTAL  (SM_BF + 2 * BF_BUF)    // 66560 -> 2 CTAs/SM

// ---------------- kernel 0: zero scores + context region --------------------
__global__ void zero_kernel(float* __restrict__ ctx) {
    int i = blockIdx.x * blockDim.x + threadIdx.x;
    if (i < BS_)      g_scores[i] = 0.0f;
    if (i < B_ * H_)  ctx[i]      = 0.0f;
}

// ---------------- kernel 1: bias2 = hidden @ W^T + b_attn -------------------
__global__ void bias2_kernel(const float* __restrict__ hidden,
                             const float* __restrict__ W,
                             const float* __restrict__ b_attn) {
    __shared__ float sh[H_];
    const int b = blockIdx.x;
    for (int i = threadIdx.x; i < H_; i += blockDim.x) sh[i] = hidden[b * H_ + i];
    __syncthreads();

    const int w    = threadIdx.x >> 5;
    const int lane = threadIdx.x & 31;
    const int o    = blockIdx.y * 8 + w;
    const float* wr = W + (size_t)o * H_;

    float sum = 0.0f;
#pragma unroll
    for (int h = lane * 4; h < H_; h += 128) {
        float4 wv = *(const float4*)(wr + h);
        float4 xv = *(const float4*)(sh + h);
        sum += wv.x * xv.x + wv.y * xv.y + wv.z * xv.z + wv.w * xv.w;
    }
#pragma unroll
    for (int off = 16; off; off >>= 1)
        sum += __shfl_xor_sync(0xffffffffu, sum, off);
    if (lane == 0) g_bias2[b * H_ + o] = sum + b_attn[o];
}

// ---------------- kernel 2: LDG fp32 -> reg bf16 split -> mma.sync ----------
// scores[b,s] += sum_o v[o]*tanh(enc[s]·W[o] + bias2[b,o])
// bf16x3: x*w ~ xh*wh + xh*wl + xl*wh. CTA 128x128, K-chunk 32, 2 CTAs/SM.
__device__ __forceinline__ float fast_tanh(float x) {
    float t = __expf(-2.0f * fabsf(x));
    float r = __fdividef(1.0f - t, 1.0f + t);
    return copysignf(r, x);
}

__global__ void __launch_bounds__(256, 2)
energy_mma(const float* __restrict__ enc, const float* __restrict__ W,
           const float* __restrict__ v) {
    extern __shared__ __align__(1024) char smem[];
    const uint32_t sb  = smem_u32(smem);
    const int tid  = threadIdx.x;
    const int wid  = tid >> 5;
    const int lane = tid & 31;
    const int oBase   = blockIdx.x * 128;
    const int rowBase = blockIdx.y * 128;
    const int b       = rowBase >> 11;

    const int warpM = (wid >> 2) * 64;   // 0 or 64
    const int warpN = (wid & 3) * 32;    // 0,32,64,96

    if (tid < 128) {
        ((float*)(smem + SM_BIAS))[tid] = g_bias2[b * H_ + oBase + tid];
        ((float*)(smem + SM_V))[tid]    = v[oBase + tid];
    }

    // ---- conversion mapping: 8 threads per row (coalesced float4 loads),
    // 32 rows per pass, 4 passes each for A and B.
    const int crow = tid >> 3;           // 0..31
    const int cf   = tid & 7;            // float4 index within 32-float chunk
    const float* aSrc = enc + (size_t)(rowBase + crow) * H_ + cf * 4;
    const float* bSrc = W   + (size_t)(oBase  + crow) * H_ + cf * 4;
    uint32_t dOff[4];
#pragma unroll
    for (int p = 0; p < 4; ++p) {
        const int row = p * 32 + crow;
        dOff[p] = row * 64 + (((cf >> 1) ^ ((row >> 1) & 3)) << 4) + (cf & 1) * 8;
    }

    // ---- mma fragment mapping (validated R6)
    const int rA = (lane & 7) + (((lane >> 3) & 1) << 3);
    const int gA = (lane >> 4) & 1;
    const int rB = (lane & 7) + (((lane >> 4) & 1) << 3);
    const int gB = (lane >> 3) & 1;
    const int xA2 = (rA >> 1) & 3;
    const int xB2 = (rB >> 1) & 3;

    float acc[4][4][4];
#pragma unroll
    for (int i = 0; i < 4; ++i)
#pragma unroll
        for (int j = 0; j < 4; ++j)
#pragma unroll
            for (int k = 0; k < 4; ++k) acc[i][j][k] = 0.0f;

    // conversion of chunk c into buffer bufsel
#define CONVERT_CHUNK(c, bufsel)                                               \
    do {                                                                       \
        char* _buf = (char*)smem + SM_BF + (bufsel) * BF_BUF;                  \
        _Pragma("unroll")                                                      \
        for (int p = 0; p < 4; ++p) {                                          \
            float4 x = *(const float4*)(aSrc + (size_t)p * 32 * H_ + (c) * 32);\
            uint2 hw, lw;                                                      \
            hw.x = pack_bf16(x.x, x.y);  hw.y = pack_bf16(x.z, x.w);           \
            lw.x = pack_bf16(x.x - tob(x.x), x.y - tob(x.y));                  \
            lw.y = pack_bf16(x.z - tob(x.z), x.w - tob(x.w));                  \
            *(uint2*)(_buf + dOff[p])          = hw;                           \
            *(uint2*)(_buf + BF_ALO + dOff[p]) = lw;                           \
        }                                                                      \
        _Pragma("unroll")                                                      \
        for (int p = 0; p < 4; ++p) {                                          \
            float4 x = *(const float4*)(bSrc + (size_t)p * 32 * H_ + (c) * 32);\
            uint2 hw, lw;                                                      \
            hw.x = pack_bf16(x.x, x.y);  hw.y = pack_bf16(x.z, x.w);           \
            lw.x = pack_bf16(x.x - tob(x.x), x.y - tob(x.y));                  \
            lw.y = pack_bf16(x.z - tob(x.z), x.w - tob(x.w));                  \
            *(uint2*)(_buf + BF_BHI + dOff[p]) = hw;                           \
            *(uint2*)(_buf + BF_BLO + dOff[p]) = lw;                           \
        }                                                                      \
    } while (0)

    // ---- prologue: chunk 0 -> buf 0
    CONVERT_CHUNK(0, 0);
    __syncthreads();

#pragma unroll 1
    for (int kt = 0; kt < 32; ++kt) {
        // convert chunk kt+1 into buf (kt+1)&1 (that buffer's MMA finished
        // before the previous __syncthreads)
        if (kt + 1 < 32) CONVERT_CHUNK(kt + 1, (kt + 1) & 1);

        // mma on bf16 buf kt&1 (written last iteration, synced)
        {
            const uint32_t bufb = sb + SM_BF + (kt & 1) * BF_BUF;
            const uint32_t AH = bufb;
            const uint32_t AL = bufb + BF_ALO;
            const uint32_t BH = bufb + BF_BHI;
            const uint32_t BL = bufb + BF_BLO;
#pragma unroll
            for (int k16 = 0; k16 < 2; ++k16) {
                const int cA = ((2 * k16 + gA) ^ xA2) << 4;
                const int cB = ((2 * k16 + gB) ^ xB2) << 4;
                uint32_t ah[4][4], bh[2][4], bl[2][4];
#pragma unroll
                for (int mi = 0; mi < 4; ++mi)
                    ldsm4(ah[mi], AH + (warpM + mi * 16 + rA) * 64 + cA);
#pragma unroll
                for (int np = 0; np < 2; ++np)
                    ldsm4(bh[np], BH + (warpN + np * 16 + rB) * 64 + cB);
#pragma unroll
                for (int np = 0; np < 2; ++np)
                    ldsm4(bl[np], BL + (warpN + np * 16 + rB) * 64 + cB);
                // p0: Ahi x Bhi, p1: Ahi x Blo (ah dies after these)
#pragma unroll
                for (int mi = 0; mi < 4; ++mi)
#pragma unroll
                    for (int ni = 0; ni < 4; ++ni) {
                        mma16816(acc[mi][ni], ah[mi],
                                 bh[ni >> 1][(ni & 1) * 2], bh[ni >> 1][(ni & 1) * 2 + 1]);
                        mma16816(acc[mi][ni], ah[mi],
                                 bl[ni >> 1][(ni & 1) * 2], bl[ni >> 1][(ni & 1) * 2 + 1]);
                    }
                // p2: Alo x Bhi (al reuses ah's registers)
                uint32_t al[4][4];
#pragma unroll
                for (int mi = 0; mi < 4; ++mi)
                    ldsm4(al[mi], AL + (warpM + mi * 16 + rA) * 64 + cA);
#pragma unroll
                for (int mi = 0; mi < 4; ++mi)
#pragma unroll
                    for (int ni = 0; ni < 4; ++ni)
                        mma16816(acc[mi][ni], al[mi],
                                 bh[ni >> 1][(ni & 1) * 2], bh[ni >> 1][(ni & 1) * 2 + 1]);
            }
        }
        __syncthreads();
    }

    // ---- epilogue: tanh(acc + bias2)*v, reduce over n, atomicAdd scores ----
    const float* sbias = (const float*)(smem + SM_BIAS);
    const float* sv    = (const float*)(smem + SM_V);
    const int q = lane & 3;
    const int r = lane >> 2;

#pragma unroll
    for (int mi = 0; mi < 4; ++mi) {
        float pa = 0.0f, pb = 0.0f;
#pragma unroll
        for (int ni = 0; ni < 4; ++ni) {
            const int n0 = warpN + ni * 8 + 2 * q;
            const float b0 = sbias[n0], b1 = sbias[n0 + 1];
            const float v0 = sv[n0],    v1 = sv[n0 + 1];
            pa += fast_tanh(acc[mi][ni][0] + b0) * v0 +
                  fast_tanh(acc[mi][ni][1] + b1) * v1;
            pb += fast_tanh(acc[mi][ni][2] + b0) * v0 +
                  fast_tanh(acc[mi][ni][3] + b1) * v1;
        }
        pa += __shfl_xor_sync(0xffffffffu, pa, 1);
        pa += __shfl_xor_sync(0xffffffffu, pa, 2);
        pb += __shfl_xor_sync(0xffffffffu, pb, 1);
        pb += __shfl_xor_sync(0xffffffffu, pb, 2);
        if (q == 0) {
            const int m = rowBase + warpM + mi * 16 + r;
            atomicAdd(&g_scores[m], pa);
            atomicAdd(&g_scores[m + 8], pb);
        }
    }
}

// ---------------- kernel 3: softmax over S per batch ------------------------
__global__ void softmax_kernel(float* __restrict__ attn) {
    __shared__ float red[8];
    const int b = blockIdx.x, t = threadIdx.x;
    const float* s = g_scores + b * S_;

    float loc[8];
    float mx = -1e30f;
#pragma unroll
    for (int i = 0; i < 8; ++i) {
        loc[i] = s[t + i * 256];
        mx = fmaxf(mx, loc[i]);
    }
#pragma unroll
    for (int off = 16; off; off >>= 1)
        mx = fmaxf(mx, __shfl_xor_sync(0xffffffffu, mx, off));
    if ((t & 31) == 0) red[t >> 5] = mx;
    __syncthreads();
    float bm = red[0];
#pragma unroll
    for (int w = 1; w < 8; ++w) bm = fmaxf(bm, red[w]);
    __syncthreads();

    float sum = 0.0f;
#pragma unroll
    for (int i = 0; i < 8; ++i) {
        loc[i] = expf(loc[i] - bm);
        sum += loc[i];
    }
#pragma unroll
    for (int off = 16; off; off >>= 1)
        sum += __shfl_xor_sync(0xffffffffu, sum, off);
    if ((t & 31) == 0) red[t >> 5] = sum;
    __syncthreads();
    float bs = 0.0f;
#pragma unroll
    for (int w = 0; w < 8; ++w) bs += red[w];

    const float inv = 1.0f / bs;
#pragma unroll
    for (int i = 0; i < 8; ++i)
        attn[b * S_ + t + i * 256] = loc[i] * inv;
}

// ---------------- kernel 4: context = attn @ enc ----------------------------
__global__ void context_kernel(const float* __restrict__ enc,
                               const float* __restrict__ attn,
                               float* __restrict__ ctx) {
    __shared__ float ws[128];
    const int b  = blockIdx.x;
    const int s0 = blockIdx.y * 128;
    if (threadIdx.x < 128) ws[threadIdx.x] = attn[b * S_ + s0 + threadIdx.x];
    __syncthreads();

    const int h = threadIdx.x * 4;
    float4 acc = make_float4(0.f, 0.f, 0.f, 0.f);
    const float* base = enc + ((size_t)b * S_ + s0) * H_ + h;
#pragma unroll 4
    for (int s = 0; s < 128; ++s) {
        const float w = ws[s];
        float4 e = *(const float4*)(base + (size_t)s * H_);
        acc.x += w * e.x;  acc.y += w * e.y;
        acc.z += w * e.z;  acc.w += w * e.w;
    }
    atomicAdd(&ctx[b * H_ + h + 0], acc.x);
    atomicAdd(&ctx[b * H_ + h + 1], acc.y);
    atomicAdd(&ctx[b * H_ + h + 2], acc.z);
    atomicAdd(&ctx[b * H_ + h + 3], acc.w);
}

// ---------------- launch ----------------------------------------------------
extern "C" void kernel_launch(void* const* d_in, const int* in_sizes, int n_in,
                              void* d_out, int out_size) {
    const float* hidden = (const float*)d_in[0];   // [B,H]
    const float* enc    = (const float*)d_in[1];   // [B,S,H]
    const float* W      = (const float*)d_in[2];   // [H,H]
    const float* b_attn = (const float*)d_in[3];   // [H]
    const float* v      = (const float*)d_in[4];   // [H]

    float* out  = (float*)d_out;
    float* ctx  = out;             // [B,H]
    float* attn = out + B_ * H_;   // [B,S]

    // idempotent, executed every call (no static guards)
    cudaFuncSetAttribute((const void*)energy_mma,
                         cudaFuncAttributeMaxDynamicSharedMemorySize, SM_TOTAL);

    zero_kernel<<<256, 256>>>(ctx);
    bias2_kernel<<<dim3(B_, H_ / 8), 256>>>(hidden, W, b_attn);
    energy_mma<<<dim3(H_ / 128, BS_ / 128), 256, SM_TOTAL>>>(enc, W, v);
    softmax_kernel<<<B_, 256>>>(attn);
    context_kernel<<<dim3(B_, 16), 256>>>(enc, attn, ctx);
}

// round 8
// speedup vs baseline: 2.3846x; 1.0526x over previous
#include <cuda_runtime.h>
#include <cuda_bf16.h>
#include <math.h>
#include <stdint.h>

#define B_  32
#define S_  2048
#define H_  1024
#define BS_ (B_ * S_)

// ---------------- scratch (small device globals only) -----------------------
__device__ __align__(1024) float g_scores[BS_];     // [B,S] logits
__device__ __align__(1024) float g_bias2[B_ * H_];  // [B,H]

// =================== PTX helpers ============================================
__device__ __forceinline__ uint32_t smem_u32(const void* p) {
    uint32_t a;
    asm("{ .reg .u64 t; cvta.to.shared.u64 t, %1; cvt.u32.u64 %0, t; }"
        : "=r"(a) : "l"(p));
    return a;
}
__device__ __forceinline__ void ldsm4(uint32_t r[4], uint32_t addr) {
    asm volatile("ldmatrix.sync.aligned.m8n8.x4.shared.b16 {%0,%1,%2,%3}, [%4];"
                 : "=r"(r[0]), "=r"(r[1]), "=r"(r[2]), "=r"(r[3]) : "r"(addr));
}
__device__ __forceinline__ void mma16816(float c[4], const uint32_t a[4],
                                         uint32_t b0, uint32_t b1) {
    asm volatile(
        "mma.sync.aligned.m16n8k16.row.col.f32.bf16.bf16.f32 "
        "{%0,%1,%2,%3}, {%4,%5,%6,%7}, {%8,%9}, {%0,%1,%2,%3};"
        : "+f"(c[0]), "+f"(c[1]), "+f"(c[2]), "+f"(c[3])
        : "r"(a[0]), "r"(a[1]), "r"(a[2]), "r"(a[3]), "r"(b0), "r"(b1));
}
__device__ __forceinline__ uint32_t pack_bf16(float lo_e, float hi_e) {
    uint32_t r;   // word = {lo half = bf16(lo_e), hi half = bf16(hi_e)}
    asm("cvt.rn.bf16x2.f32 %0, %1, %2;" : "=r"(r) : "f"(hi_e), "f"(lo_e));
    return r;
}
__device__ __forceinline__ uint32_t prmt_hi(uint32_t a, uint32_t b) {
    uint32_t r;   // word = {lo half = a[31:16], hi half = b[31:16]} (bf16 trunc)
    asm("prmt.b32 %0, %1, %2, 0x7632;" : "=r"(r) : "r"(a), "r"(b));
    return r;
}
__device__ __forceinline__ void cp_async16(uint32_t dst, const void* src) {
    asm volatile("cp.async.cg.shared.global [%0], [%1], 16;"
                 :: "r"(dst), "l"(src) : "memory");
}
__device__ __forceinline__ void cp_commit() {
    asm volatile("cp.async.commit_group;" ::: "memory");
}
__device__ __forceinline__ void cp_wait0() {
    asm volatile("cp.async.wait_group 0;" ::: "memory");
}

// ---------------- SMEM layout for energy_mma --------------------------------
// bias 0..512 | v 512..1024 | fp32 stage 1024..33792 (per-thread slots)
// bf16 double buffer @33792: 2 x 32KB (AH 0 | AL 8K | BH 16K | BL 24K)
#define SM_BIAS   0
#define SM_V      512
#define SM_F32    1024
#define SM_BF     33792
#define BF_BUF    32768
#define BF_ALO    8192
#define BF_BHI    16384
#define BF_BLO    24576
#define SM_TOTAL  (SM_BF + 2 * BF_BUF)    // 99328 -> 2 CTAs/SM

// ---------------- kernel 0: zero scores + context region --------------------
__global__ void zero_kernel(float* __restrict__ ctx) {
    int i = blockIdx.x * blockDim.x + threadIdx.x;
    if (i < BS_)      g_scores[i] = 0.0f;
    if (i < B_ * H_)  ctx[i]      = 0.0f;
}

// ---------------- kernel 1: bias2 = hidden @ W^T + b_attn -------------------
__global__ void bias2_kernel(const float* __restrict__ hidden,
                             const float* __restrict__ W,
                             const float* __restrict__ b_attn) {
    __shared__ float sh[H_];
    const int b = blockIdx.x;
    for (int i = threadIdx.x; i < H_; i += blockDim.x) sh[i] = hidden[b * H_ + i];
    __syncthreads();

    const int w    = threadIdx.x >> 5;
    const int lane = threadIdx.x & 31;
    const int o    = blockIdx.y * 8 + w;
    const float* wr = W + (size_t)o * H_;

    float sum = 0.0f;
#pragma unroll
    for (int h = lane * 4; h < H_; h += 128) {
        float4 wv = *(const float4*)(wr + h);
        float4 xv = *(const float4*)(sh + h);
        sum += wv.x * xv.x + wv.y * xv.y + wv.z * xv.z + wv.w * xv.w;
    }
#pragma unroll
    for (int off = 16; off; off >>= 1)
        sum += __shfl_xor_sync(0xffffffffu, sum, off);
    if (lane == 0) g_bias2[b * H_ + o] = sum + b_attn[o];
}

// ---------------- kernel 2: cp.async fp32 -> bitwise bf16 split -> mma ------
// scores[b,s] += sum_o v[o]*tanh(enc[s]·W[o] + bias2[b,o])
// bf16x3: x*w ~ xh*wh + xh*wl + xl*wh, xh = truncate(x), xl = x - xh (exact).
__device__ __forceinline__ float fast_tanh(float x) {
    float t = __expf(-2.0f * fabsf(x));
    float r = __fdividef(1.0f - t, 1.0f + t);
    return copysignf(r, x);
}

__global__ void __launch_bounds__(256, 2)
energy_mma(const float* __restrict__ enc, const float* __restrict__ W,
           const float* __restrict__ v) {
    extern __shared__ __align__(1024) char smem[];
    const uint32_t sb  = smem_u32(smem);
    const int tid  = threadIdx.x;
    const int wid  = tid >> 5;
    const int lane = tid & 31;
    const int oBase   = blockIdx.x * 128;
    const int rowBase = blockIdx.y * 128;
    const int b       = rowBase >> 11;

    const int warpM = (wid >> 2) * 64;
    const int warpN = (wid & 3) * 32;

    if (tid < 128) {
        ((float*)(smem + SM_BIAS))[tid] = g_bias2[b * H_ + oBase + tid];
        ((float*)(smem + SM_V))[tid]    = v[oBase + tid];
    }

    // ---- staging: 8 float4 slots per thread, interleaved for conflict-free LDS
    const int crow = tid >> 3;           // 0..31
    const int cf   = tid & 7;            // float4 index within 32-float chunk
    const float* aSrc = enc + (size_t)(rowBase + crow) * H_ + cf * 4;
    const float* bSrc = W   + (size_t)(oBase  + crow) * H_ + cf * 4;
#define SLOT(j) (sb + SM_F32 + ((((j) << 8) + tid) << 4))
    uint32_t dOff[4];
#pragma unroll
    for (int p = 0; p < 4; ++p) {
        const int row = p * 32 + crow;
        dOff[p] = row * 64 + (((cf >> 1) ^ ((row >> 1) & 3)) << 4) + (cf & 1) * 8;
    }

    // issue cp.async for chunk c (A -> slots 0..3, B -> slots 4..7)
#define CP_CHUNK(c)                                                            \
    do {                                                                       \
        _Pragma("unroll")                                                      \
        for (int p = 0; p < 4; ++p)                                            \
            cp_async16(SLOT(p), aSrc + (size_t)p * 32 * H_ + (c) * 32);        \
        _Pragma("unroll")                                                      \
        for (int p = 0; p < 4; ++p)                                            \
            cp_async16(SLOT(4 + p), bSrc + (size_t)p * 32 * H_ + (c) * 32);    \
        cp_commit();                                                           \
    } while (0)

    // convert staged chunk -> bf16 buffer bufsel (bitwise truncation split)
#define CONVERT_STAGE(bufsel)                                                  \
    do {                                                                       \
        char* _buf = (char*)smem + SM_BF + (bufsel) * BF_BUF;                  \
        cp_wait0();                                                            \
        _Pragma("unroll")                                                      \
        for (int j = 0; j < 8; ++j) {                                          \
            float4 x;                                                          \
            asm volatile("ld.shared.v4.b32 {%0,%1,%2,%3}, [%4];"               \
                : "=f"(x.x), "=f"(x.y), "=f"(x.z), "=f"(x.w) : "r"(SLOT(j)));  \
            uint32_t u0 = __float_as_uint(x.x), u1 = __float_as_uint(x.y);     \
            uint32_t u2 = __float_as_uint(x.z), u3 = __float_as_uint(x.w);     \
            uint2 hw, lw;                                                      \
            hw.x = prmt_hi(u0, u1);  hw.y = prmt_hi(u2, u3);                   \
            float l0 = x.x - __uint_as_float(u0 & 0xffff0000u);                \
            float l1 = x.y - __uint_as_float(u1 & 0xffff0000u);                \
            float l2 = x.z - __uint_as_float(u2 & 0xffff0000u);                \
            float l3 = x.w - __uint_as_float(u3 & 0xffff0000u);                \
            lw.x = pack_bf16(l0, l1);  lw.y = pack_bf16(l2, l3);               \
            const int _p = j & 3;                                              \
            const uint32_t _base = (j < 4) ? dOff[_p] : (16384u + dOff[_p]);   \
            *(uint2*)(_buf + _base)        = hw;                               \
            *(uint2*)(_buf + _base + 8192) = lw;                               \
        }                                                                      \
    } while (0)

    // ---- mma fragment mapping (validated R6/R7)
    const int rA = (lane & 7) + (((lane >> 3) & 1) << 3);
    const int gA = (lane >> 4) & 1;
    const int rB = (lane & 7) + (((lane >> 4) & 1) << 3);
    const int gB = (lane >> 3) & 1;
    const int xA2 = (rA >> 1) & 3;
    const int xB2 = (rB >> 1) & 3;

    float acc[4][4][4];
#pragma unroll
    for (int i = 0; i < 4; ++i)
#pragma unroll
        for (int j = 0; j < 4; ++j)
#pragma unroll
            for (int k = 0; k < 4; ++k) acc[i][j][k] = 0.0f;

    // ---- prologue: chunk 0 staged+converted, chunk 1 in flight
    CP_CHUNK(0);
    CONVERT_STAGE(0);
    CP_CHUNK(1);
    __syncthreads();

#pragma unroll 1
    for (int kt = 0; kt < 32; ++kt) {
        // convert chunk kt+1 (staged last iteration) into buf (kt+1)&1;
        // then prefetch chunk kt+2 into the freed slots
        if (kt + 1 < 32) CONVERT_STAGE((kt + 1) & 1);
        if (kt + 2 < 32) CP_CHUNK(kt + 2);

        // mma on bf16 buf kt&1 (written last iteration, synced)
        {
            const uint32_t bufb = sb + SM_BF + (kt & 1) * BF_BUF;
            const uint32_t AH = bufb;
            const uint32_t AL = bufb + BF_ALO;
            const uint32_t BH = bufb + BF_BHI;
            const uint32_t BL = bufb + BF_BLO;
#pragma unroll
            for (int k16 = 0; k16 < 2; ++k16) {
                const int cA = ((2 * k16 + gA) ^ xA2) << 4;
                const int cB = ((2 * k16 + gB) ^ xB2) << 4;
                uint32_t ah[4][4], bh[2][4], bl[2][4];
#pragma unroll
                for (int mi = 0; mi < 4; ++mi)
                    ldsm4(ah[mi], AH + (warpM + mi * 16 + rA) * 64 + cA);
#pragma unroll
                for (int np = 0; np < 2; ++np)
                    ldsm4(bh[np], BH + (warpN + np * 16 + rB) * 64 + cB);
#pragma unroll
                for (int np = 0; np < 2; ++np)
                    ldsm4(bl[np], BL + (warpN + np * 16 + rB) * 64 + cB);
#pragma unroll
                for (int mi = 0; mi < 4; ++mi)
#pragma unroll
                    for (int ni = 0; ni < 4; ++ni) {
                        mma16816(acc[mi][ni], ah[mi],
                                 bh[ni >> 1][(ni & 1) * 2], bh[ni >> 1][(ni & 1) * 2 + 1]);
                        mma16816(acc[mi][ni], ah[mi],
                                 bl[ni >> 1][(ni & 1) * 2], bl[ni >> 1][(ni & 1) * 2 + 1]);
                    }
                uint32_t al[4][4];
#pragma unroll
                for (int mi = 0; mi < 4; ++mi)
                    ldsm4(al[mi], AL + (warpM + mi * 16 + rA) * 64 + cA);
#pragma unroll
                for (int mi = 0; mi < 4; ++mi)
#pragma unroll
                    for (int ni = 0; ni < 4; ++ni)
                        mma16816(acc[mi][ni], al[mi],
                                 bh[ni >> 1][(ni & 1) * 2], bh[ni >> 1][(ni & 1) * 2 + 1]);
            }
        }
        __syncthreads();
    }

    // ---- epilogue: tanh(acc + bias2)*v, reduce over n, atomicAdd scores ----
    const float* sbias = (const float*)(smem + SM_BIAS);
    const float* sv    = (const float*)(smem + SM_V);
    const int q = lane & 3;
    const int r = lane >> 2;

#pragma unroll
    for (int mi = 0; mi < 4; ++mi) {
        float pa = 0.0f, pb = 0.0f;
#pragma unroll
        for (int ni = 0; ni < 4; ++ni) {
            const int n0 = warpN + ni * 8 + 2 * q;
            const float b0 = sbias[n0], b1 = sbias[n0 + 1];
            const float v0 = sv[n0],    v1 = sv[n0 + 1];
            pa += fast_tanh(acc[mi][ni][0] + b0) * v0 +
                  fast_tanh(acc[mi][ni][1] + b1) * v1;
            pb += fast_tanh(acc[mi][ni][2] + b0) * v0 +
                  fast_tanh(acc[mi][ni][3] + b1) * v1;
        }
        pa += __shfl_xor_sync(0xffffffffu, pa, 1);
        pa += __shfl_xor_sync(0xffffffffu, pa, 2);
        pb += __shfl_xor_sync(0xffffffffu, pb, 1);
        pb += __shfl_xor_sync(0xffffffffu, pb, 2);
        if (q == 0) {
            const int m = rowBase + warpM + mi * 16 + r;
            atomicAdd(&g_scores[m], pa);
            atomicAdd(&g_scores[m + 8], pb);
        }
    }
}

// ---------------- kernel 3: softmax over S per batch ------------------------
__global__ void softmax_kernel(float* __restrict__ attn) {
    __shared__ float red[8];
    const int b = blockIdx.x, t = threadIdx.x;
    const float* s = g_scores + b * S_;

    float loc[8];
    float mx = -1e30f;
#pragma unroll
    for (int i = 0; i < 8; ++i) {
        loc[i] = s[t + i * 256];
        mx = fmaxf(mx, loc[i]);
    }
#pragma unroll
    for (int off = 16; off; off >>= 1)
        mx = fmaxf(mx, __shfl_xor_sync(0xffffffffu, mx, off));
    if ((t & 31) == 0) red[t >> 5] = mx;
    __syncthreads();
    float bm = red[0];
#pragma unroll
    for (int w = 1; w < 8; ++w) bm = fmaxf(bm, red[w]);
    __syncthreads();

    float sum = 0.0f;
#pragma unroll
    for (int i = 0; i < 8; ++i) {
        loc[i] = expf(loc[i] - bm);
        sum += loc[i];
    }
#pragma unroll
    for (int off = 16; off; off >>= 1)
        sum += __shfl_xor_sync(0xffffffffu, sum, off);
    if ((t & 31) == 0) red[t >> 5] = sum;
    __syncthreads();
    float bs = 0.0f;
#pragma unroll
    for (int w = 0; w < 8; ++w) bs += red[w];

    const float inv = 1.0f / bs;
#pragma unroll
    for (int i = 0; i < 8; ++i)
        attn[b * S_ + t + i * 256] = loc[i] * inv;
}

// ---------------- kernel 4: context = attn @ enc ----------------------------
__global__ void context_kernel(const float* __restrict__ enc,
                               const float* __restrict__ attn,
                               float* __restrict__ ctx) {
    __shared__ float ws[128];
    const int b  = blockIdx.x;
    const int s0 = blockIdx.y * 128;
    if (threadIdx.x < 128) ws[threadIdx.x] = attn[b * S_ + s0 + threadIdx.x];
    __syncthreads();

    const int h = threadIdx.x * 4;
    float4 acc = make_float4(0.f, 0.f, 0.f, 0.f);
    const float* base = enc + ((size_t)b * S_ + s0) * H_ + h;
#pragma unroll 4
    for (int s = 0; s < 128; ++s) {
        const float w = ws[s];
        float4 e = *(const float4*)(base + (size_t)s * H_);
        acc.x += w * e.x;  acc.y += w * e.y;
        acc.z += w * e.z;  acc.w += w * e.w;
    }
    atomicAdd(&ctx[b * H_ + h + 0], acc.x);
    atomicAdd(&ctx[b * H_ + h + 1], acc.y);
    atomicAdd(&ctx[b * H_ + h + 2], acc.z);
    atomicAdd(&ctx[b * H_ + h + 3], acc.w);
}

// ---------------- launch ----------------------------------------------------
extern "C" void kernel_launch(void* const* d_in, const int* in_sizes, int n_in,
                              void* d_out, int out_size) {
    const float* hidden = (const float*)d_in[0];   // [B,H]
    const float* enc    = (const float*)d_in[1];   // [B,S,H]
    const float* W      = (const float*)d_in[2];   // [H,H]
    const float* b_attn = (const float*)d_in[3];   // [H]
    const float* v      = (const float*)d_in[4];   // [H]

    float* out  = (float*)d_out;
    float* ctx  = out;             // [B,H]
    float* attn = out + B_ * H_;   // [B,S]

    // idempotent, executed every call (no static guards)
    cudaFuncSetAttribute((const void*)energy_mma,
                         cudaFuncAttributeMaxDynamicSharedMemorySize, SM_TOTAL);

    zero_kernel<<<256, 256>>>(ctx);
    bias2_kernel<<<dim3(B_, H_ / 8), 256>>>(hidden, W, b_attn);
    energy_mma<<<dim3(H_ / 128, BS_ / 128), 256, SM_TOTAL>>>(enc, W, v);
    softmax_kernel<<<B_, 256>>>(attn);
    context_kernel<<<dim3(B_, 16), 256>>>(enc, attn, ctx);
}

// round 10
// speedup vs baseline: 2.4457x; 1.0256x over previous
#include <cuda_runtime.h>
#include <cuda_bf16.h>
#include <math.h>
#include <stdint.h>

#define B_  32
#define S_  2048
#define H_  1024
#define BS_ (B_ * S_)

// ---------------- scratch (small device globals only) -----------------------
__device__ __align__(1024) float g_scores[BS_];     // [B,S] logits
__device__ __align__(1024) float g_bias2[B_ * H_];  // [B,H]

// =================== PTX helpers ============================================
__device__ __forceinline__ uint32_t smem_u32(const void* p) {
    uint32_t a;
    asm("{ .reg .u64 t; cvta.to.shared.u64 t, %1; cvt.u32.u64 %0, t; }"
        : "=r"(a) : "l"(p));
    return a;
}
__device__ __forceinline__ void ldsm4(uint32_t r[4], uint32_t addr) {
    asm volatile("ldmatrix.sync.aligned.m8n8.x4.shared.b16 {%0,%1,%2,%3}, [%4];"
                 : "=r"(r[0]), "=r"(r[1]), "=r"(r[2]), "=r"(r[3]) : "r"(addr));
}
__device__ __forceinline__ void mma16816(float c[4], const uint32_t a[4],
                                         uint32_t b0, uint32_t b1) {
    asm volatile(
        "mma.sync.aligned.m16n8k16.row.col.f32.bf16.bf16.f32 "
        "{%0,%1,%2,%3}, {%4,%5,%6,%7}, {%8,%9}, {%0,%1,%2,%3};"
        : "+f"(c[0]), "+f"(c[1]), "+f"(c[2]), "+f"(c[3])
        : "r"(a[0]), "r"(a[1]), "r"(a[2]), "r"(a[3]), "r"(b0), "r"(b1));
}
__device__ __forceinline__ uint32_t pack_bf16(float lo_e, float hi_e) {
    uint32_t r;
    asm("cvt.rn.bf16x2.f32 %0, %1, %2;" : "=r"(r) : "f"(hi_e), "f"(lo_e));
    return r;
}
__device__ __forceinline__ uint32_t prmt_hi(uint32_t a, uint32_t b) {
    uint32_t r;   // {lo half = a[31:16], hi half = b[31:16]} (bf16 trunc)
    asm("prmt.b32 %0, %1, %2, 0x7632;" : "=r"(r) : "r"(a), "r"(b));
    return r;
}
__device__ __forceinline__ void cp_async16(uint32_t dst, const void* src) {
    asm volatile("cp.async.cg.shared.global [%0], [%1], 16;"
                 :: "r"(dst), "l"(src) : "memory");
}
__device__ __forceinline__ void cp_commit() {
    asm volatile("cp.async.commit_group;" ::: "memory");
}
__device__ __forceinline__ void cp_wait0() {
    asm volatile("cp.async.wait_group 0;" ::: "memory");
}

// bitwise bf16x2 split of one float4: hi = truncate (prmt), lo = rn(x - hi).
// dst_hi points at the hi-plane location; lo plane is +8192 bytes.
__device__ __forceinline__ void split_store(const float4 val, char* dst_hi) {
    const uint32_t u0 = __float_as_uint(val.x), u1 = __float_as_uint(val.y);
    const uint32_t u2 = __float_as_uint(val.z), u3 = __float_as_uint(val.w);
    uint2 hw, lw;
    hw.x = prmt_hi(u0, u1);
    hw.y = prmt_hi(u2, u3);
    const float l0 = val.x - __uint_as_float(u0 & 0xffff0000u);
    const float l1 = val.y - __uint_as_float(u1 & 0xffff0000u);
    const float l2 = val.z - __uint_as_float(u2 & 0xffff0000u);
    const float l3 = val.w - __uint_as_float(u3 & 0xffff0000u);
    lw.x = pack_bf16(l0, l1);
    lw.y = pack_bf16(l2, l3);
    *(uint2*)(dst_hi)        = hw;
    *(uint2*)(dst_hi + 8192) = lw;
}

// ---------------- SMEM layout for energy_mma --------------------------------
// bias 0..512 | v 512..1024 | B fp32 slots 1024..17408 |
// bf16 double buffer @17408: 2 x 32KB (AH 0 | AL 8K | BH 16K | BL 24K)
#define SM_BIAS   0
#define SM_V      512
#define SM_F32    1024
#define SM_BF     17408
#define BF_BUF    32768
#define BF_BHI    16384
#define SM_TOTAL  (SM_BF + 2 * BF_BUF)    // 82944 -> 2 CTAs/SM

// ---------------- kernel 0: zero scores + context region --------------------
__global__ void zero_kernel(float* __restrict__ ctx) {
    int i = blockIdx.x * blockDim.x + threadIdx.x;
    if (i < BS_)      g_scores[i] = 0.0f;
    if (i < B_ * H_)  ctx[i]      = 0.0f;
}

// ---------------- kernel 1: bias2 = hidden @ W^T + b_attn -------------------
__global__ void bias2_kernel(const float* __restrict__ hidden,
                             const float* __restrict__ W,
                             const float* __restrict__ b_attn) {
    __shared__ float sh[H_];
    const int b = blockIdx.x;
    for (int i = threadIdx.x; i < H_; i += blockDim.x) sh[i] = hidden[b * H_ + i];
    __syncthreads();

    const int w    = threadIdx.x >> 5;
    const int lane = threadIdx.x & 31;
    const int o    = blockIdx.y * 8 + w;
    const float* wr = W + (size_t)o * H_;

    float sum = 0.0f;
#pragma unroll
    for (int h = lane * 4; h < H_; h += 128) {
        float4 wv = *(const float4*)(wr + h);
        float4 xv = *(const float4*)(sh + h);
        sum += wv.x * xv.x + wv.y * xv.y + wv.z * xv.z + wv.w * xv.w;
    }
#pragma unroll
    for (int off = 16; off; off >>= 1)
        sum += __shfl_xor_sync(0xffffffffu, sum, off);
    if (lane == 0) g_bias2[b * H_ + o] = sum + b_attn[o];
}

// ---------------- kernel 2: A via LDG->regs, B via cp.async -> mma ----------
// scores[b,s] += sum_o v[o]*tanh(enc[s]·W[o] + bias2[b,o])
// bf16x3: x*w ~ xh*wh + xh*wl + xl*wh, xh = truncate(x), xl = rn(x - xh).
__device__ __forceinline__ float fast_tanh(float x) {
    float t = __expf(-2.0f * fabsf(x));
    float r = __fdividef(1.0f - t, 1.0f + t);
    return copysignf(r, x);
}

__global__ void __launch_bounds__(256, 2)
energy_mma(const float* __restrict__ enc, const float* __restrict__ W,
           const float* __restrict__ v) {
    extern __shared__ __align__(1024) char smem[];
    const uint32_t sb  = smem_u32(smem);
    const int tid  = threadIdx.x;
    const int wid  = tid >> 5;
    const int lane = tid & 31;
    const int oBase   = blockIdx.x * 128;
    const int rowBase = blockIdx.y * 128;
    const int b       = rowBase >> 11;

    const int warpM = (wid >> 2) * 64;
    const int warpN = (wid & 3) * 32;

    if (tid < 128) {
        ((float*)(smem + SM_BIAS))[tid] = g_bias2[b * H_ + oBase + tid];
        ((float*)(smem + SM_V))[tid]    = v[oBase + tid];
    }

    // ---- loader mapping: 8 threads/row, 32 rows/pass, 4 passes
    const int crow = tid >> 3;           // 0..31
    const int cf   = tid & 7;            // float4 index within 32-float chunk
    const float* aSrc = enc + (size_t)(rowBase + crow) * H_ + cf * 4;
    const float* bSrc = W   + (size_t)(oBase  + crow) * H_ + cf * 4;
#define SLOT(j) (sb + SM_F32 + ((((j) << 8) + tid) << 4))
    uint32_t dOff[4];
#pragma unroll
    for (int p = 0; p < 4; ++p) {
        const int row = p * 32 + crow;
        dOff[p] = row * 64 + (((cf >> 1) ^ ((row >> 1) & 3)) << 4) + (cf & 1) * 8;
    }

    // A chunk prefetch registers (live across one MMA block)
    float4 areg[4];

#define LDG_A(c)                                                               \
    do {                                                                       \
        _Pragma("unroll")                                                      \
        for (int p = 0; p < 4; ++p)                                            \
            areg[p] = *(const float4*)(aSrc + (size_t)p * 32 * H_ + (c) * 32); \
    } while (0)

#define CP_B(c)                                                                \
    do {                                                                       \
        _Pragma("unroll")                                                      \
        for (int p = 0; p < 4; ++p)                                            \
            cp_async16(SLOT(p), bSrc + (size_t)p * 32 * H_ + (c) * 32);        \
        cp_commit();                                                           \
    } while (0)

    // convert A (from regs) + B (from slots) into bf16 buffer bufsel
#define CONVERT(bufsel)                                                        \
    do {                                                                       \
        char* _buf = (char*)smem + SM_BF + (bufsel) * BF_BUF;                  \
        cp_wait0();                                                            \
        _Pragma("unroll")                                                      \
        for (int p = 0; p < 4; ++p) split_store(areg[p], _buf + dOff[p]);      \
        _Pragma("unroll")                                                      \
        for (int j = 0; j < 4; ++j) {                                          \
            float4 bx;                                                         \
            asm volatile("ld.shared.v4.b32 {%0,%1,%2,%3}, [%4];"               \
                : "=f"(bx.x), "=f"(bx.y), "=f"(bx.z), "=f"(bx.w)               \
                : "r"(SLOT(j)));                                               \
            split_store(bx, _buf + BF_BHI + dOff[j]);                          \
        }                                                                      \
    } while (0)

    // ---- mma fragment mapping (validated R6-R8)
    const int rA = (lane & 7) + (((lane >> 3) & 1) << 3);
    const int gA = (lane >> 4) & 1;
    const int rB = (lane & 7) + (((lane >> 4) & 1) << 3);
    const int gB = (lane >> 3) & 1;
    const int xA2 = (rA >> 1) & 3;
    const int xB2 = (rB >> 1) & 3;

    float acc[4][4][4];
#pragma unroll
    for (int i = 0; i < 4; ++i)
#pragma unroll
        for (int j = 0; j < 4; ++j)
#pragma unroll
            for (int k = 0; k < 4; ++k) acc[i][j][k] = 0.0f;

    // ---- prologue: chunk 0 converted into buf 0; chunk 1 in flight
    CP_B(0);
    LDG_A(0);
    CONVERT(0);
    CP_B(1);
    LDG_A(1);
    __syncthreads();

#pragma unroll 1
    for (int kt = 0; kt < 32; ++kt) {
        // mma on bf16 buf kt&1 (ready; synced). areg holds chunk kt+1.
        {
            const uint32_t bufb = sb + SM_BF + (kt & 1) * BF_BUF;
            const uint32_t AH = bufb;
            const uint32_t AL = bufb + 8192;
            const uint32_t BH = bufb + BF_BHI;
            const uint32_t BL = bufb + BF_BHI + 8192;
#pragma unroll
            for (int k16 = 0; k16 < 2; ++k16) {
                const int cA = ((2 * k16 + gA) ^ xA2) << 4;
                const int cB = ((2 * k16 + gB) ^ xB2) << 4;
                uint32_t ah[4][4], bh[2][4], bl[2][4];
#pragma unroll
                for (int mi = 0; mi < 4; ++mi)
                    ldsm4(ah[mi], AH + (warpM + mi * 16 + rA) * 64 + cA);
#pragma unroll
                for (int np = 0; np < 2; ++np)
                    ldsm4(bh[np], BH + (warpN + np * 16 + rB) * 64 + cB);
#pragma unroll
                for (int np = 0; np < 2; ++np)
                    ldsm4(bl[np], BL + (warpN + np * 16 + rB) * 64 + cB);
#pragma unroll
                for (int mi = 0; mi < 4; ++mi)
#pragma unroll
                    for (int ni = 0; ni < 4; ++ni) {
                        mma16816(acc[mi][ni], ah[mi],
                                 bh[ni >> 1][(ni & 1) * 2], bh[ni >> 1][(ni & 1) * 2 + 1]);
                        mma16816(acc[mi][ni], ah[mi],
                                 bl[ni >> 1][(ni & 1) * 2], bl[ni >> 1][(ni & 1) * 2 + 1]);
                    }
                uint32_t al[4][4];
#pragma unroll
                for (int mi = 0; mi < 4; ++mi)
                    ldsm4(al[mi], AL + (warpM + mi * 16 + rA) * 64 + cA);
#pragma unroll
                for (int mi = 0; mi < 4; ++mi)
#pragma unroll
                    for (int ni = 0; ni < 4; ++ni)
                        mma16816(acc[mi][ni], al[mi],
                                 bh[ni >> 1][(ni & 1) * 2], bh[ni >> 1][(ni & 1) * 2 + 1]);
            }
        }

        // convert chunk kt+1 into buf (kt+1)&1, then start chunk kt+2 loads
        if (kt + 1 < 32) CONVERT((kt + 1) & 1);
        if (kt + 2 < 32) {
            CP_B(kt + 2);
            LDG_A(kt + 2);
        }
        __syncthreads();
    }

    // ---- epilogue: tanh(acc + bias2)*v, reduce over n, atomicAdd scores ----
    const float* sbias = (const float*)(smem + SM_BIAS);
    const float* sv    = (const float*)(smem + SM_V);
    const int q = lane & 3;
    const int r = lane >> 2;

#pragma unroll
    for (int mi = 0; mi < 4; ++mi) {
        float pa = 0.0f, pb = 0.0f;
#pragma unroll
        for (int ni = 0; ni < 4; ++ni) {
            const int n0 = warpN + ni * 8 + 2 * q;
            const float b0 = sbias[n0], b1 = sbias[n0 + 1];
            const float v0 = sv[n0],    v1 = sv[n0 + 1];
            pa += fast_tanh(acc[mi][ni][0] + b0) * v0 +
                  fast_tanh(acc[mi][ni][1] + b1) * v1;
            pb += fast_tanh(acc[mi][ni][2] + b0) * v0 +
                  fast_tanh(acc[mi][ni][3] + b1) * v1;
        }
        pa += __shfl_xor_sync(0xffffffffu, pa, 1);
        pa += __shfl_xor_sync(0xffffffffu, pa, 2);
        pb += __shfl_xor_sync(0xffffffffu, pb, 1);
        pb += __shfl_xor_sync(0xffffffffu, pb, 2);
        if (q == 0) {
            const int m = rowBase + warpM + mi * 16 + r;
            atomicAdd(&g_scores[m], pa);
            atomicAdd(&g_scores[m + 8], pb);
        }
    }
}

// ---------------- kernel 3: softmax over S per batch ------------------------
__global__ void softmax_kernel(float* __restrict__ attn) {
    __shared__ float red[8];
    const int b = blockIdx.x, t = threadIdx.x;
    const float* s = g_scores + b * S_;

    float loc[8];
    float mx = -1e30f;
#pragma unroll
    for (int i = 0; i < 8; ++i) {
        loc[i] = s[t + i * 256];
        mx = fmaxf(mx, loc[i]);
    }
#pragma unroll
    for (int off = 16; off; off >>= 1)
        mx = fmaxf(mx, __shfl_xor_sync(0xffffffffu, mx, off));
    if ((t & 31) == 0) red[t >> 5] = mx;
    __syncthreads();
    float bm = red[0];
#pragma unroll
    for (int w = 1; w < 8; ++w) bm = fmaxf(bm, red[w]);
    __syncthreads();

    float sum = 0.0f;
#pragma unroll
    for (int i = 0; i < 8; ++i) {
        loc[i] = expf(loc[i] - bm);
        sum += loc[i];
    }
#pragma unroll
    for (int off = 16; off; off >>= 1)
        sum += __shfl_xor_sync(0xffffffffu, sum, off);
    if ((t & 31) == 0) red[t >> 5] = sum;
    __syncthreads();
    float bs = 0.0f;
#pragma unroll
    for (int w = 0; w < 8; ++w) bs += red[w];

    const float inv = 1.0f / bs;
#pragma unroll
    for (int i = 0; i < 8; ++i)
        attn[b * S_ + t + i * 256] = loc[i] * inv;
}

// ---------------- kernel 4: context = attn @ enc ----------------------------
__global__ void context_kernel(const float* __restrict__ enc,
                               const float* __restrict__ attn,
                               float* __restrict__ ctx) {
    __shared__ float ws[128];
    const int b  = blockIdx.x;
    const int s0 = blockIdx.y * 128;
    if (threadIdx.x < 128) ws[threadIdx.x] = attn[b * S_ + s0 + threadIdx.x];
    __syncthreads();

    const int h = threadIdx.x * 4;
    float4 acc = make_float4(0.f, 0.f, 0.f, 0.f);
    const float* base = enc + ((size_t)b * S_ + s0) * H_ + h;
#pragma unroll 4
    for (int s = 0; s < 128; ++s) {
        const float w = ws[s];
        float4 e = *(const float4*)(base + (size_t)s * H_);
        acc.x += w * e.x;  acc.y += w * e.y;
        acc.z += w * e.z;  acc.w += w * e.w;
    }
    atomicAdd(&ctx[b * H_ + h + 0], acc.x);
    atomicAdd(&ctx[b * H_ + h + 1], acc.y);
    atomicAdd(&ctx[b * H_ + h + 2], acc.z);
    atomicAdd(&ctx[b * H_ + h + 3], acc.w);
}

// ---------------- launch ----------------------------------------------------
extern "C" void kernel_launch(void* const* d_in, const int* in_sizes, int n_in,
                              void* d_out, int out_size) {
    const float* hidden = (const float*)d_in[0];   // [B,H]
    const float* enc    = (const float*)d_in[1];   // [B,S,H]
    const float* W      = (const float*)d_in[2];   // [H,H]
    const float* b_attn = (const float*)d_in[3];   // [H]
    const float* v      = (const float*)d_in[4];   // [H]

    float* out  = (float*)d_out;
    float* ctx  = out;             // [B,H]
    float* attn = out + B_ * H_;   // [B,S]

    // idempotent, executed every call (no static guards)
    cudaFuncSetAttribute((const void*)energy_mma,
                         cudaFuncAttributeMaxDynamicSharedMemorySize, SM_TOTAL);

    zero_kernel<<<256, 256>>>(ctx);
    bias2_kernel<<<dim3(B_, H_ / 8), 256>>>(hidden, W, b_attn);
    energy_mma<<<dim3(H_ / 128, BS_ / 128), 256, SM_TOTAL>>>(enc, W, v);
    softmax_kernel<<<B_, 256>>>(attn);
    context_kernel<<<dim3(B_, 16), 256>>>(enc, attn, ctx);
}

// round 11
// speedup vs baseline: 3.3266x; 1.3602x over previous
#include <cuda_runtime.h>
#include <cuda_fp16.h>
#include <math.h>
#include <stdint.h>

#define B_  32
#define S_  2048
#define H_  1024
#define BS_ (B_ * S_)

// ---------------- scratch (small device globals only) -----------------------
__device__ __align__(1024) float g_scores[BS_];     // [B,S] logits
__device__ __align__(1024) float g_bias2[B_ * H_];  // [B,H]

// =================== PTX helpers ============================================
__device__ __forceinline__ uint32_t smem_u32(const void* p) {
    uint32_t a;
    asm("{ .reg .u64 t; cvta.to.shared.u64 t, %1; cvt.u32.u64 %0, t; }"
        : "=r"(a) : "l"(p));
    return a;
}
__device__ __forceinline__ void ldsm4(uint32_t r[4], uint32_t addr) {
    asm volatile("ldmatrix.sync.aligned.m8n8.x4.shared.b16 {%0,%1,%2,%3}, [%4];"
                 : "=r"(r[0]), "=r"(r[1]), "=r"(r[2]), "=r"(r[3]) : "r"(addr));
}
__device__ __forceinline__ void mma16816(float c[4], const uint32_t a[4],
                                         uint32_t b0, uint32_t b1) {
    asm volatile(
        "mma.sync.aligned.m16n8k16.row.col.f32.f16.f16.f32 "
        "{%0,%1,%2,%3}, {%4,%5,%6,%7}, {%8,%9}, {%0,%1,%2,%3};"
        : "+f"(c[0]), "+f"(c[1]), "+f"(c[2]), "+f"(c[3])
        : "r"(a[0]), "r"(a[1]), "r"(a[2]), "r"(a[3]), "r"(b0), "r"(b1));
}
__device__ __forceinline__ void cp_async16(uint32_t dst, const void* src) {
    asm volatile("cp.async.cg.shared.global [%0], [%1], 16;"
                 :: "r"(dst), "l"(src) : "memory");
}
__device__ __forceinline__ void cp_commit() {
    asm volatile("cp.async.commit_group;" ::: "memory");
}
__device__ __forceinline__ void cp_wait0() {
    asm volatile("cp.async.wait_group 0;" ::: "memory");
}

// fp16 rn split of one float4: xh = rn_f16(x), xl = rn_f16(x - xh).
// dst_hi = hi-plane location; lo plane is +8192 bytes.
__device__ __forceinline__ void split_store_f16(const float4 val, char* dst_hi) {
    const __half h0 = __float2half_rn(val.x);
    const __half h1 = __float2half_rn(val.y);
    const __half h2 = __float2half_rn(val.z);
    const __half h3 = __float2half_rn(val.w);
    __half2 hw0 = __halves2half2(h0, h1);
    __half2 hw1 = __halves2half2(h2, h3);
    const __half l0 = __float2half_rn(val.x - __half2float(h0));
    const __half l1 = __float2half_rn(val.y - __half2float(h1));
    const __half l2 = __float2half_rn(val.z - __half2float(h2));
    const __half l3 = __float2half_rn(val.w - __half2float(h3));
    __half2 lw0 = __halves2half2(l0, l1);
    __half2 lw1 = __halves2half2(l2, l3);
    ((__half2*)dst_hi)[0] = hw0;
    ((__half2*)dst_hi)[1] = hw1;
    ((__half2*)(dst_hi + 8192))[0] = lw0;
    ((__half2*)(dst_hi + 8192))[1] = lw1;
}

// single-plane fp16 rn convert of one float4
__device__ __forceinline__ void cvt_store_f16(const float4 val, char* dst) {
    __half2 w0 = __halves2half2(__float2half_rn(val.x), __float2half_rn(val.y));
    __half2 w1 = __halves2half2(__float2half_rn(val.z), __float2half_rn(val.w));
    ((__half2*)dst)[0] = w0;
    ((__half2*)dst)[1] = w1;
}

// ---------------- SMEM layout for energy_mma --------------------------------
// bias 0..512 | v 512..1024 | B fp32 slots 1024..17408 |
// fp16 double buffer @17408: 2 x 24KB (AH 0 | AL 8K | BH 16K)
#define SM_BIAS   0
#define SM_V      512
#define SM_F32    1024
#define SM_BF     17408
#define BF_BUF    24576
#define BF_BH     16384
#define SM_TOTAL  (SM_BF + 2 * BF_BUF)    // 66560 -> 2 CTAs/SM

// ---------------- kernel 0: zero scores + context region --------------------
__global__ void zero_kernel(float* __restrict__ ctx) {
    int i = blockIdx.x * blockDim.x + threadIdx.x;
    if (i < BS_)      g_scores[i] = 0.0f;
    if (i < B_ * H_)  ctx[i]      = 0.0f;
}

// ---------------- kernel 1: bias2 = hidden @ W^T + b_attn -------------------
__global__ void bias2_kernel(const float* __restrict__ hidden,
                             const float* __restrict__ W,
                             const float* __restrict__ b_attn) {
    __shared__ float sh[H_];
    const int b = blockIdx.x;
    for (int i = threadIdx.x; i < H_; i += blockDim.x) sh[i] = hidden[b * H_ + i];
    __syncthreads();

    const int w    = threadIdx.x >> 5;
    const int lane = threadIdx.x & 31;
    const int o    = blockIdx.y * 8 + w;
    const float* wr = W + (size_t)o * H_;

    float sum = 0.0f;
#pragma unroll
    for (int h = lane * 4; h < H_; h += 128) {
        float4 wv = *(const float4*)(wr + h);
        float4 xv = *(const float4*)(sh + h);
        sum += wv.x * xv.x + wv.y * xv.y + wv.z * xv.z + wv.w * xv.w;
    }
#pragma unroll
    for (int off = 16; off; off >>= 1)
        sum += __shfl_xor_sync(0xffffffffu, sum, off);
    if (lane == 0) g_bias2[b * H_ + o] = sum + b_attn[o];
}

// ---------------- kernel 2: fp16 2-product split GEMM + tanh + dot(v) -------
// scores[b,s] += sum_o v[o]*tanh(enc[s]·W[o] + bias2[b,o])
// x*w ~ xh*wh + xl*wh (= x*wh exactly); dropped term x*wl ~ 2^-12.
__device__ __forceinline__ float fast_tanh(float x) {
    float t = __expf(-2.0f * fabsf(x));
    float r = __fdividef(1.0f - t, 1.0f + t);
    return copysignf(r, x);
}

__global__ void __launch_bounds__(256, 2)
energy_mma(const float* __restrict__ enc, const float* __restrict__ W,
           const float* __restrict__ v) {
    extern __shared__ __align__(1024) char smem[];
    const uint32_t sb  = smem_u32(smem);
    const int tid  = threadIdx.x;
    const int wid  = tid >> 5;
    const int lane = tid & 31;
    const int oBase   = blockIdx.x * 128;
    const int rowBase = blockIdx.y * 128;
    const int b       = rowBase >> 11;

    const int warpM = (wid >> 2) * 64;
    const int warpN = (wid & 3) * 32;

    if (tid < 128) {
        ((float*)(smem + SM_BIAS))[tid] = g_bias2[b * H_ + oBase + tid];
        ((float*)(smem + SM_V))[tid]    = v[oBase + tid];
    }

    // ---- loader mapping: 8 threads/row, 32 rows/pass, 4 passes
    const int crow = tid >> 3;           // 0..31
    const int cf   = tid & 7;            // float4 index within 32-float chunk
    const float* aSrc = enc + (size_t)(rowBase + crow) * H_ + cf * 4;
    const float* bSrc = W   + (size_t)(oBase  + crow) * H_ + cf * 4;
#define SLOT(j) (sb + SM_F32 + ((((j) << 8) + tid) << 4))
    uint32_t dOff[4];
#pragma unroll
    for (int p = 0; p < 4; ++p) {
        const int row = p * 32 + crow;
        dOff[p] = row * 64 + (((cf >> 1) ^ ((row >> 1) & 3)) << 4) + (cf & 1) * 8;
    }

    // A chunk prefetch registers (live across one MMA block)
    float4 areg[4];

#define LDG_A(c)                                                               \
    do {                                                                       \
        _Pragma("unroll")                                                      \
        for (int p = 0; p < 4; ++p)                                            \
            areg[p] = *(const float4*)(aSrc + (size_t)p * 32 * H_ + (c) * 32); \
    } while (0)

#define CP_B(c)                                                                \
    do {                                                                       \
        _Pragma("unroll")                                                      \
        for (int p = 0; p < 4; ++p)                                            \
            cp_async16(SLOT(p), bSrc + (size_t)p * 32 * H_ + (c) * 32);        \
        cp_commit();                                                           \
    } while (0)

    // convert A (from regs, 2 planes) + B (from slots, 1 plane) into buffer
#define CONVERT(bufsel)                                                        \
    do {                                                                       \
        char* _buf = (char*)smem + SM_BF + (bufsel) * BF_BUF;                  \
        cp_wait0();                                                            \
        _Pragma("unroll")                                                      \
        for (int p = 0; p < 4; ++p) split_store_f16(areg[p], _buf + dOff[p]);  \
        _Pragma("unroll")                                                      \
        for (int j = 0; j < 4; ++j) {                                          \
            float4 bx;                                                         \
            asm volatile("ld.shared.v4.b32 {%0,%1,%2,%3}, [%4];"               \
                : "=f"(bx.x), "=f"(bx.y), "=f"(bx.z), "=f"(bx.w)               \
                : "r"(SLOT(j)));                                               \
            cvt_store_f16(bx, _buf + BF_BH + dOff[j]);                         \
        }                                                                      \
    } while (0)

    // ---- mma fragment mapping (validated R6-R10)
    const int rA = (lane & 7) + (((lane >> 3) & 1) << 3);
    const int gA = (lane >> 4) & 1;
    const int rB = (lane & 7) + (((lane >> 4) & 1) << 3);
    const int gB = (lane >> 3) & 1;
    const int xA2 = (rA >> 1) & 3;
    const int xB2 = (rB >> 1) & 3;

    float acc[4][4][4];
#pragma unroll
    for (int i = 0; i < 4; ++i)
#pragma unroll
        for (int j = 0; j < 4; ++j)
#pragma unroll
            for (int k = 0; k < 4; ++k) acc[i][j][k] = 0.0f;

    // ---- prologue: chunk 0 converted into buf 0; chunk 1 in flight
    CP_B(0);
    LDG_A(0);
    CONVERT(0);
    CP_B(1);
    LDG_A(1);
    __syncthreads();

#pragma unroll 1
    for (int kt = 0; kt < 32; ++kt) {
        // mma on fp16 buf kt&1 (ready; synced). areg holds chunk kt+1.
        {
            const uint32_t bufb = sb + SM_BF + (kt & 1) * BF_BUF;
            const uint32_t AH = bufb;
            const uint32_t AL = bufb + 8192;
            const uint32_t BH = bufb + BF_BH;
#pragma unroll
            for (int k16 = 0; k16 < 2; ++k16) {
                const int cA = ((2 * k16 + gA) ^ xA2) << 4;
                const int cB = ((2 * k16 + gB) ^ xB2) << 4;
                uint32_t ah[4][4], bh[2][4];
#pragma unroll
                for (int mi = 0; mi < 4; ++mi)
                    ldsm4(ah[mi], AH + (warpM + mi * 16 + rA) * 64 + cA);
#pragma unroll
                for (int np = 0; np < 2; ++np)
                    ldsm4(bh[np], BH + (warpN + np * 16 + rB) * 64 + cB);
                // product 1: xh * wh
#pragma unroll
                for (int mi = 0; mi < 4; ++mi)
#pragma unroll
                    for (int ni = 0; ni < 4; ++ni)
                        mma16816(acc[mi][ni], ah[mi],
                                 bh[ni >> 1][(ni & 1) * 2], bh[ni >> 1][(ni & 1) * 2 + 1]);
                // product 2: xl * wh (al reuses ah's registers)
                uint32_t al[4][4];
#pragma unroll
                for (int mi = 0; mi < 4; ++mi)
                    ldsm4(al[mi], AL + (warpM + mi * 16 + rA) * 64 + cA);
#pragma unroll
                for (int mi = 0; mi < 4; ++mi)
#pragma unroll
                    for (int ni = 0; ni < 4; ++ni)
                        mma16816(acc[mi][ni], al[mi],
                                 bh[ni >> 1][(ni & 1) * 2], bh[ni >> 1][(ni & 1) * 2 + 1]);
            }
        }

        // convert chunk kt+1 into buf (kt+1)&1, then start chunk kt+2 loads
        if (kt + 1 < 32) CONVERT((kt + 1) & 1);
        if (kt + 2 < 32) {
            CP_B(kt + 2);
            LDG_A(kt + 2);
        }
        __syncthreads();
    }

    // ---- epilogue: tanh(acc + bias2)*v, reduce over n, atomicAdd scores ----
    const float* sbias = (const float*)(smem + SM_BIAS);
    const float* sv    = (const float*)(smem + SM_V);
    const int q = lane & 3;
    const int r = lane >> 2;

#pragma unroll
    for (int mi = 0; mi < 4; ++mi) {
        float pa = 0.0f, pb = 0.0f;
#pragma unroll
        for (int ni = 0; ni < 4; ++ni) {
            const int n0 = warpN + ni * 8 + 2 * q;
            const float b0 = sbias[n0], b1 = sbias[n0 + 1];
            const float v0 = sv[n0],    v1 = sv[n0 + 1];
            pa += fast_tanh(acc[mi][ni][0] + b0) * v0 +
                  fast_tanh(acc[mi][ni][1] + b1) * v1;
            pb += fast_tanh(acc[mi][ni][2] + b0) * v0 +
                  fast_tanh(acc[mi][ni][3] + b1) * v1;
        }
        pa += __shfl_xor_sync(0xffffffffu, pa, 1);
        pa += __shfl_xor_sync(0xffffffffu, pa, 2);
        pb += __shfl_xor_sync(0xffffffffu, pb, 1);
        pb += __shfl_xor_sync(0xffffffffu, pb, 2);
        if (q == 0) {
            const int m = rowBase + warpM + mi * 16 + r;
            atomicAdd(&g_scores[m], pa);
            atomicAdd(&g_scores[m + 8], pb);
        }
    }
}

// ---------------- kernel 3: softmax over S per batch ------------------------
__global__ void softmax_kernel(float* __restrict__ attn) {
    __shared__ float red[8];
    const int b = blockIdx.x, t = threadIdx.x;
    const float* s = g_scores + b * S_;

    float loc[8];
    float mx = -1e30f;
#pragma unroll
    for (int i = 0; i < 8; ++i) {
        loc[i] = s[t + i * 256];
        mx = fmaxf(mx, loc[i]);
    }
#pragma unroll
    for (int off = 16; off; off >>= 1)
        mx = fmaxf(mx, __shfl_xor_sync(0xffffffffu, mx, off));
    if ((t & 31) == 0) red[t >> 5] = mx;
    __syncthreads();
    float bm = red[0];
#pragma unroll
    for (int w = 1; w < 8; ++w) bm = fmaxf(bm, red[w]);
    __syncthreads();

    float sum = 0.0f;
#pragma unroll
    for (int i = 0; i < 8; ++i) {
        loc[i] = expf(loc[i] - bm);
        sum += loc[i];
    }
#pragma unroll
    for (int off = 16; off; off >>= 1)
        sum += __shfl_xor_sync(0xffffffffu, sum, off);
    if ((t & 31) == 0) red[t >> 5] = sum;
    __syncthreads();
    float bs = 0.0f;
#pragma unroll
    for (int w = 0; w < 8; ++w) bs += red[w];

    const float inv = 1.0f / bs;
#pragma unroll
    for (int i = 0; i < 8; ++i)
        attn[b * S_ + t + i * 256] = loc[i] * inv;
}

// ---------------- kernel 4: context = attn @ enc ----------------------------
__global__ void context_kernel(const float* __restrict__ enc,
                               const float* __restrict__ attn,
                               float* __restrict__ ctx) {
    __shared__ float ws[128];
    const int b  = blockIdx.x;
    const int s0 = blockIdx.y * 128;
    if (threadIdx.x < 128) ws[threadIdx.x] = attn[b * S_ + s0 + threadIdx.x];
    __syncthreads();

    const int h = threadIdx.x * 4;
    float4 acc = make_float4(0.f, 0.f, 0.f, 0.f);
    const float* base = enc + ((size_t)b * S_ + s0) * H_ + h;
#pragma unroll 4
    for (int s = 0; s < 128; ++s) {
        const float w = ws[s];
        float4 e = *(const float4*)(base + (size_t)s * H_);
        acc.x += w * e.x;  acc.y += w * e.y;
        acc.z += w * e.z;  acc.w += w * e.w;
    }
    atomicAdd(&ctx[b * H_ + h + 0], acc.x);
    atomicAdd(&ctx[b * H_ + h + 1], acc.y);
    atomicAdd(&ctx[b * H_ + h + 2], acc.z);
    atomicAdd(&ctx[b * H_ + h + 3], acc.w);
}

// ---------------- launch ----------------------------------------------------
extern "C" void kernel_launch(void* const* d_in, const int* in_sizes, int n_in,
                              void* d_out, int out_size) {
    const float* hidden = (const float*)d_in[0];   // [B,H]
    const float* enc    = (const float*)d_in[1];   // [B,S,H]
    const float* W      = (const float*)d_in[2];   // [H,H]
    const float* b_attn = (const float*)d_in[3];   // [H]
    const float* v      = (const float*)d_in[4];   // [H]

    float* out  = (float*)d_out;
    float* ctx  = out;             // [B,H]
    float* attn = out + B_ * H_;   // [B,S]

    // idempotent, executed every call (no static guards)
    cudaFuncSetAttribute((const void*)energy_mma,
                         cudaFuncAttributeMaxDynamicSharedMemorySize, SM_TOTAL);

    zero_kernel<<<256, 256>>>(ctx);
    bias2_kernel<<<dim3(B_, H_ / 8), 256>>>(hidden, W, b_attn);
    energy_mma<<<dim3(H_ / 128, BS_ / 128), 256, SM_TOTAL>>>(enc, W, v);
    softmax_kernel<<<B_, 256>>>(attn);
    context_kernel<<<dim3(B_, 16), 256>>>(enc, attn, ctx);
}